// round 6
// baseline (speedup 1.0000x reference)
#include <cuda_runtime.h>
#include <cuda_fp16.h>
#include <mma.h>
#include <cstdint>
#include <cstddef>

using namespace nvcuda;

// Problem constants
#define BATCH 2
#define SEQ   2048
#define DIM   1024
#define NH    16
#define HD    64
#define ATT_SCALE 0.125f
#define MBW   (SEQ / 32)

// Scratch
__device__ float g_Q[BATCH * SEQ * DIM];
__device__ float g_K[BATCH * SEQ * DIM];
__device__ float g_V[BATCH * SEQ * DIM];
__device__ float g_Ctx[BATCH * SEQ * DIM];
__device__ uint32_t g_MB[SEQ * MBW];

// fast exp on the FMA pipe
__device__ __forceinline__ float fast_exp(float x) {
    float n = rintf(x * 1.4426950408889634f);
    float r = fmaf(n, -0.6931471805599453f, x);
    float e = fmaf(r, 8.3333337e-3f, 4.1666668e-2f);
    e = fmaf(r, e, 0.16666667f);
    e = fmaf(r, e, 0.5f);
    e = fmaf(r, e, 1.0f);
    e = fmaf(r, e, 1.0f);
    int ni = (int)n;
    return e * __int_as_float((ni + 127) << 23);
}

// ---------------------------------------------------------------------------
// mask (int32) -> bitmask words
// ---------------------------------------------------------------------------
__global__ __launch_bounds__(256)
void mask_bits_kernel(const int* __restrict__ mask)
{
    int idx = blockIdx.x * 256 + threadIdx.x;
    uint32_t bit = (mask[idx] != 0) ? 1u : 0u;
    uint32_t word = __ballot_sync(0xffffffffu, bit);
    if ((threadIdx.x & 31) == 0) g_MB[idx >> 5] = word;
}

// ---------------------------------------------------------------------------
// FP16 GEMM + bias: C = A @ W + bias. 128x64x32 tile, double-buffered smem,
// 8 warps (4m x 2n), warp 32x32 via wmma m16n16k16 (fp32 acc).
// Manual epilogue uses the mma.sync acc layout:
//   x[g*4+{0,1}] -> (row lane>>2,   cols g*8 + 2*(lane&3) + {0,1})
//   x[g*4+{2,3}] -> (row lane>>2+8, same cols)
// blockIdx.z selects among 3 fused problems.
// ---------------------------------------------------------------------------
#define GBM 128
#define GBN 64
#define GBK 32
#define A_LDH 40    // 32 + 8 halfs
#define B_LDH 72    // 64 + 8 halfs

__global__ __launch_bounds__(256, 2)
void gemm_fp16_bias(const float* __restrict__ A0, const float* __restrict__ W0,
                    const float* __restrict__ bias0, float* __restrict__ C0,
                    const float* __restrict__ A1, const float* __restrict__ W1,
                    const float* __restrict__ bias1, float* __restrict__ C1,
                    const float* __restrict__ A2, const float* __restrict__ W2,
                    const float* __restrict__ bias2, float* __restrict__ C2,
                    int M, int N, int K)
{
    __shared__ __half As[2][GBM * A_LDH];   // 2*5120*2 = 20480B
    __shared__ __half Bs[2][GBK * B_LDH];   // 2*2304*2 =  9216B

    const int z = blockIdx.z;
    const float* A    = (z == 0) ? A0    : (z == 1) ? A1    : A2;
    const float* W    = (z == 0) ? W0    : (z == 1) ? W1    : W2;
    const float* bias = (z == 0) ? bias0 : (z == 1) ? bias1 : bias2;
    float*       C    = (z == 0) ? C0    : (z == 1) ? C1    : C2;

    const int tid  = threadIdx.x;
    const int lane = tid & 31;
    const int w    = tid >> 5;
    const int wm   = w >> 1;    // 0..3 -> 32 rows
    const int wn   = w & 1;     // 0..1 -> 32 cols
    const int row0 = blockIdx.y * GBM;
    const int col0 = blockIdx.x * GBN;

    wmma::fragment<wmma::accumulator, 16, 16, 16, float> acc[2][2];
#pragma unroll
    for (int mf = 0; mf < 2; mf++)
#pragma unroll
        for (int nf = 0; nf < 2; nf++)
            wmma::fill_fragment(acc[mf][nf], 0.f);

    // per-thread load coords
    int ar[4], ak[4];
#pragma unroll
    for (int it = 0; it < 4; it++) { int q = tid + it * 256; ar[it] = q >> 3; ak[it] = q & 7; }
    int bk_[2], bn_[2];
#pragma unroll
    for (int it = 0; it < 2; it++) { int q = tid + it * 256; bk_[it] = q >> 4; bn_[it] = q & 15; }

    // prolog: stage kt=0 into buffer 0
#pragma unroll
    for (int it = 0; it < 4; it++) {
        float4 v = *reinterpret_cast<const float4*>(A + (size_t)(row0 + ar[it]) * K + ak[it] * 4);
        __half2* dst = reinterpret_cast<__half2*>(&As[0][ar[it] * A_LDH + ak[it] * 4]);
        dst[0] = __floats2half2_rn(v.x, v.y);
        dst[1] = __floats2half2_rn(v.z, v.w);
    }
#pragma unroll
    for (int it = 0; it < 2; it++) {
        float4 v = *reinterpret_cast<const float4*>(W + (size_t)bk_[it] * N + col0 + bn_[it] * 4);
        __half2* dst = reinterpret_cast<__half2*>(&Bs[0][bk_[it] * B_LDH + bn_[it] * 4]);
        dst[0] = __floats2half2_rn(v.x, v.y);
        dst[1] = __floats2half2_rn(v.z, v.w);
    }
    __syncthreads();

    int buf = 0;
    for (int kt = 0; kt < K; kt += GBK) {
        const bool has_next = (kt + GBK) < K;
        float4 pa[4], pb[2];
        if (has_next) {
            const int kn = kt + GBK;
#pragma unroll
            for (int it = 0; it < 4; it++)
                pa[it] = *reinterpret_cast<const float4*>(A + (size_t)(row0 + ar[it]) * K + kn + ak[it] * 4);
#pragma unroll
            for (int it = 0; it < 2; it++)
                pb[it] = *reinterpret_cast<const float4*>(W + (size_t)(kn + bk_[it]) * N + col0 + bn_[it] * 4);
        }

        const __half* sA = &As[buf][0];
        const __half* sB = &Bs[buf][0];
#pragma unroll
        for (int ks = 0; ks < 2; ks++) {
            const int k0 = ks * 16;
            wmma::fragment<wmma::matrix_a, 16, 16, 16, __half, wmma::row_major> af[2];
            wmma::fragment<wmma::matrix_b, 16, 16, 16, __half, wmma::row_major> bf[2];
#pragma unroll
            for (int mf = 0; mf < 2; mf++)
                wmma::load_matrix_sync(af[mf], &sA[(wm * 32 + mf * 16) * A_LDH + k0], A_LDH);
#pragma unroll
            for (int nf = 0; nf < 2; nf++)
                wmma::load_matrix_sync(bf[nf], &sB[k0 * B_LDH + wn * 32 + nf * 16], B_LDH);
#pragma unroll
            for (int mf = 0; mf < 2; mf++)
#pragma unroll
                for (int nf = 0; nf < 2; nf++)
                    wmma::mma_sync(acc[mf][nf], af[mf], bf[nf], acc[mf][nf]);
        }

        if (has_next) {
            __half* dA = &As[buf ^ 1][0];
            __half* dB = &Bs[buf ^ 1][0];
#pragma unroll
            for (int it = 0; it < 4; it++) {
                __half2* dst = reinterpret_cast<__half2*>(&dA[ar[it] * A_LDH + ak[it] * 4]);
                dst[0] = __floats2half2_rn(pa[it].x, pa[it].y);
                dst[1] = __floats2half2_rn(pa[it].z, pa[it].w);
            }
#pragma unroll
            for (int it = 0; it < 2; it++) {
                __half2* dst = reinterpret_cast<__half2*>(&dB[bk_[it] * B_LDH + bn_[it] * 4]);
                dst[0] = __floats2half2_rn(pb[it].x, pb[it].y);
                dst[1] = __floats2half2_rn(pb[it].z, pb[it].w);
            }
        }
        __syncthreads();
        buf ^= 1;
    }

    // ---- epilogue: manual store with bias (acc layout as documented above) ----
    float2 bb[2][2];
#pragma unroll
    for (int nf = 0; nf < 2; nf++)
#pragma unroll
        for (int g = 0; g < 2; g++)
            bb[nf][g] = *reinterpret_cast<const float2*>(
                &bias[col0 + wn * 32 + nf * 16 + g * 8 + 2 * (lane & 3)]);

#pragma unroll
    for (int mf = 0; mf < 2; mf++) {
        const int r  = row0 + wm * 32 + mf * 16 + (lane >> 2);
#pragma unroll
        for (int nf = 0; nf < 2; nf++) {
#pragma unroll
            for (int g = 0; g < 2; g++) {
                const int col = col0 + wn * 32 + nf * 16 + g * 8 + 2 * (lane & 3);
                float2 lo, hi;
                lo.x = acc[mf][nf].x[g * 4 + 0] + bb[nf][g].x;
                lo.y = acc[mf][nf].x[g * 4 + 1] + bb[nf][g].y;
                hi.x = acc[mf][nf].x[g * 4 + 2] + bb[nf][g].x;
                hi.y = acc[mf][nf].x[g * 4 + 3] + bb[nf][g].y;
                *reinterpret_cast<float2*>(&C[(size_t)r * N + col])       = lo;
                *reinterpret_cast<float2*>(&C[(size_t)(r + 8) * N + col]) = hi;
            }
        }
    }
}

// ---------------------------------------------------------------------------
// Masked attention, fp16 wmma, Q-tile 128 x KV-tile 64, no max subtraction.
// exp+mask in-register on acc fragments; O written directly from fragments.
// Block: 256 threads = 8 warps (2m x 4n): wm -> 64 rows, wn -> 16 cols.
// ---------------------------------------------------------------------------
#define TSM 128
#define TSN 64
#define PADP 72

__global__ __launch_bounds__(256, 2)
void attn_fp16(float* __restrict__ Og)
{
    extern __shared__ char smraw[];
    __half* Qs = reinterpret_cast<__half*>(smraw);        // [128][72]
    __half* Ks = Qs + TSM * PADP;                         // [64][72]
    __half* Vs = Ks + TSN * PADP;                         // [64][72]
    __half* Ps = Vs + TSN * PADP;                         // [128][72]
    float*  Ls = reinterpret_cast<float*>(Ps + TSM * PADP);  // [4][128]

    const int qt = blockIdx.x;
    const int h  = blockIdx.y;
    const int b  = blockIdx.z;
    const int s0 = qt * TSM;
    const int tid  = threadIdx.x;
    const int lane = tid & 31;
    const int w    = tid >> 5;
    const int wm   = w >> 2;   // 0..1 : 64 rows
    const int wn   = w & 3;    // 0..3 : 16 cols

    const float* Qbase = g_Q + ((size_t)b * SEQ + s0) * DIM + h * HD;
    const float* Kbase = g_K + (size_t)b * SEQ * DIM + h * HD;
    const float* Vbase = g_V + (size_t)b * SEQ * DIM + h * HD;

    // load Q tile (fold ATT_SCALE): 128x64 = 2048 float4, 8/thread
#pragma unroll
    for (int it = 0; it < 8; it++) {
        int lin = tid + it * 256;
        int row = lin >> 4, q4 = lin & 15;
        float4 v = *reinterpret_cast<const float4*>(Qbase + (size_t)row * DIM + q4 * 4);
        __half2* dst = reinterpret_cast<__half2*>(&Qs[row * PADP + q4 * 4]);
        dst[0] = __floats2half2_rn(v.x * ATT_SCALE, v.y * ATT_SCALE);
        dst[1] = __floats2half2_rn(v.z * ATT_SCALE, v.w * ATT_SCALE);
    }

    wmma::fragment<wmma::accumulator, 16, 16, 16, float> ofrag[4];
#pragma unroll
    for (int f = 0; f < 4; f++) wmma::fill_fragment(ofrag[f], 0.f);

    float lsum[4][2];
#pragma unroll
    for (int f = 0; f < 4; f++) { lsum[f][0] = 0.f; lsum[f][1] = 0.f; }

    const int wrow = s0 + wm * 64 + (lane >> 2);
    const int sh   = (wn & 1) * 16;

    for (int kt = 0; kt < SEQ; kt += TSN) {
        // ---- load K / V tiles: 64x64 each, 4 float4/thread each ----
#pragma unroll
        for (int it = 0; it < 4; it++) {
            int lin = tid + it * 256;
            int row = lin >> 4, q4 = lin & 15;
            float4 kv = *reinterpret_cast<const float4*>(Kbase + (size_t)(kt + row) * DIM + q4 * 4);
            float4 vv = *reinterpret_cast<const float4*>(Vbase + (size_t)(kt + row) * DIM + q4 * 4);
            __half2* dk = reinterpret_cast<__half2*>(&Ks[row * PADP + q4 * 4]);
            dk[0] = __floats2half2_rn(kv.x, kv.y);
            dk[1] = __floats2half2_rn(kv.z, kv.w);
            __half2* dv = reinterpret_cast<__half2*>(&Vs[row * PADP + q4 * 4]);
            dv[0] = __floats2half2_rn(vv.x, vv.y);
            dv[1] = __floats2half2_rn(vv.z, vv.w);
        }
        __syncthreads();

        // prefetch mask words (latency hidden under S mma)
        const int colw = (kt + wn * 16) >> 5;
        uint32_t mw0[4], mw8[4];
#pragma unroll
        for (int f = 0; f < 4; f++) {
            mw0[f] = g_MB[(wrow + f * 16) * MBW + colw];
            mw8[f] = g_MB[(wrow + f * 16 + 8) * MBW + colw];
        }

        // ---- S = (Q*scale) @ K^T ----
        wmma::fragment<wmma::accumulator, 16, 16, 16, float> sfrag[4];
#pragma unroll
        for (int f = 0; f < 4; f++) wmma::fill_fragment(sfrag[f], 0.f);

#pragma unroll
        for (int d0 = 0; d0 < HD; d0 += 16) {
            wmma::fragment<wmma::matrix_b, 16, 16, 16, __half, wmma::col_major> bkf;
            wmma::load_matrix_sync(bkf, &Ks[(wn * 16) * PADP + d0], PADP);
#pragma unroll
            for (int f = 0; f < 4; f++) {
                wmma::fragment<wmma::matrix_a, 16, 16, 16, __half, wmma::row_major> aq;
                wmma::load_matrix_sync(aq, &Qs[(wm * 64 + f * 16) * PADP + d0], PADP);
                wmma::mma_sync(sfrag[f], aq, bkf, sfrag[f]);
            }
        }

        // ---- in-register masked exp + partial row sums; store P (half) ----
#pragma unroll
        for (int f = 0; f < 4; f++) {
            uint32_t b0 = (mw0[f] >> sh) & 0xFFFFu;
            uint32_t b8 = (mw8[f] >> sh) & 0xFFFFu;
            float rs0 = 0.f, rs8 = 0.f;
            const int prow = wm * 64 + f * 16 + (lane >> 2);
#pragma unroll
            for (int g = 0; g < 2; g++) {
                const int cb = g * 8 + 2 * (lane & 3);
                float p0 = ((b0 >> cb)       & 1u) ? fast_exp(sfrag[f].x[g * 4 + 0]) : 0.f;
                float p1 = ((b0 >> (cb + 1)) & 1u) ? fast_exp(sfrag[f].x[g * 4 + 1]) : 0.f;
                float p2 = ((b8 >> cb)       & 1u) ? fast_exp(sfrag[f].x[g * 4 + 2]) : 0.f;
                float p3 = ((b8 >> (cb + 1)) & 1u) ? fast_exp(sfrag[f].x[g * 4 + 3]) : 0.f;
                rs0 += p0 + p1;
                rs8 += p2 + p3;
                const int col = wn * 16 + cb;
                *reinterpret_cast<__half2*>(&Ps[prow * PADP + col])       = __floats2half2_rn(p0, p1);
                *reinterpret_cast<__half2*>(&Ps[(prow + 8) * PADP + col]) = __floats2half2_rn(p2, p3);
            }
            rs0 += __shfl_xor_sync(0xffffffffu, rs0, 1);
            rs0 += __shfl_xor_sync(0xffffffffu, rs0, 2);
            rs8 += __shfl_xor_sync(0xffffffffu, rs8, 1);
            rs8 += __shfl_xor_sync(0xffffffffu, rs8, 2);
            lsum[f][0] += rs0;
            lsum[f][1] += rs8;
        }
        __syncthreads();

        // ---- O += P @ V ----
#pragma unroll
        for (int t0 = 0; t0 < TSN; t0 += 16) {
            wmma::fragment<wmma::matrix_b, 16, 16, 16, __half, wmma::row_major> bvf;
            wmma::load_matrix_sync(bvf, &Vs[t0 * PADP + wn * 16], PADP);
#pragma unroll
            for (int f = 0; f < 4; f++) {
                wmma::fragment<wmma::matrix_a, 16, 16, 16, __half, wmma::row_major> ap;
                wmma::load_matrix_sync(ap, &Ps[(wm * 64 + f * 16) * PADP + t0], PADP);
                wmma::mma_sync(ofrag[f], ap, bvf, ofrag[f]);
            }
        }
        __syncthreads();
    }

    // ---- publish l partials ----
    if ((lane & 3) == 0) {
#pragma unroll
        for (int f = 0; f < 4; f++) {
            Ls[wn * TSM + wm * 64 + f * 16 + (lane >> 2)]     = lsum[f][0];
            Ls[wn * TSM + wm * 64 + f * 16 + (lane >> 2) + 8] = lsum[f][1];
        }
    }
    __syncthreads();

    // ---- normalize in-register, write O directly from fragments ----
#pragma unroll
    for (int f = 0; f < 4; f++) {
        const int row  = wm * 64 + f * 16 + (lane >> 2);
        const float l0 = Ls[row] + Ls[TSM + row] + Ls[2 * TSM + row] + Ls[3 * TSM + row];
        const float l8 = Ls[row + 8] + Ls[TSM + row + 8] + Ls[2 * TSM + row + 8] + Ls[3 * TSM + row + 8];
        const float inv0 = 1.f / l0;
        const float inv8 = 1.f / l8;
        float* o0 = Og + ((size_t)b * SEQ + s0 + row) * DIM + h * HD;
        float* o8 = Og + ((size_t)b * SEQ + s0 + row + 8) * DIM + h * HD;
#pragma unroll
        for (int g = 0; g < 2; g++) {
            const int col = wn * 16 + g * 8 + 2 * (lane & 3);
            float2 lo, hi;
            lo.x = ofrag[f].x[g * 4 + 0] * inv0;
            lo.y = ofrag[f].x[g * 4 + 1] * inv0;
            hi.x = ofrag[f].x[g * 4 + 2] * inv8;
            hi.y = ofrag[f].x[g * 4 + 3] * inv8;
            *reinterpret_cast<float2*>(&o0[col]) = lo;
            *reinterpret_cast<float2*>(&o8[col]) = hi;
        }
    }
}

// ---------------------------------------------------------------------------
// Launch
// ---------------------------------------------------------------------------
extern "C" void kernel_launch(void* const* d_in, const int* in_sizes, int n_in,
                              void* d_out, int out_size)
{
    const float* query = (const float*)d_in[0];
    const float* key   = (const float*)d_in[1];
    const float* value = (const float*)d_in[2];
    const int*   mask  = (const int*)  d_in[3];
    const float* Wq = (const float*)d_in[4];
    const float* bq = (const float*)d_in[5];
    const float* Wk = (const float*)d_in[6];
    const float* bk = (const float*)d_in[7];
    const float* Wv = (const float*)d_in[8];
    const float* bv = (const float*)d_in[9];
    const float* Wo = (const float*)d_in[10];
    const float* bo = (const float*)d_in[11];
    float* out = (float*)d_out;

    float *pQ, *pK, *pV, *pC;
    cudaGetSymbolAddress((void**)&pQ, g_Q);
    cudaGetSymbolAddress((void**)&pK, g_K);
    cudaGetSymbolAddress((void**)&pV, g_V);
    cudaGetSymbolAddress((void**)&pC, g_Ctx);

    const int M = BATCH * SEQ;   // 4096
    const int N = DIM;
    const int K = DIM;

    mask_bits_kernel<<<SEQ * SEQ / 256, 256>>>(mask);

    dim3 qkv_grid(N / GBN, M / GBM, 3);   // (16, 32, 3)
    gemm_fp16_bias<<<qkv_grid, 256>>>(query, Wq, bq, pQ,
                                      key,   Wk, bk, pK,
                                      value, Wv, bv, pV, M, N, K);

    const int attn_smem = (2 * TSM * PADP + 2 * TSN * PADP) * 2 + 4 * TSM * 4;  // 57344 B
    cudaFuncSetAttribute(attn_fp16, cudaFuncAttributeMaxDynamicSharedMemorySize, attn_smem);
    attn_fp16<<<dim3(SEQ / TSM, NH, BATCH), 256, attn_smem>>>(pC);

    dim3 ogrid(N / GBN, M / GBM, 1);
    gemm_fp16_bias<<<ogrid, 256>>>(pC, Wo, bo, out,
                                   pC, Wo, bo, out,
                                   pC, Wo, bo, out, M, N, K);
}

// round 7
// speedup vs baseline: 1.0115x; 1.0115x over previous
#include <cuda_runtime.h>
#include <cuda_fp16.h>
#include <mma.h>
#include <cstdint>
#include <cstddef>

using namespace nvcuda;

// Problem constants
#define BATCH 2
#define SEQ   2048
#define DIM   1024
#define NH    16
#define HD    64
#define ATT_SCALE 0.125f
#define MBW   (SEQ / 32)

// Scratch: fp16 storage for all intermediates
__device__ __half g_Qh[BATCH * SEQ * DIM];
__device__ __half g_Kh[BATCH * SEQ * DIM];
__device__ __half g_Vh[BATCH * SEQ * DIM];
__device__ __half g_Ch[BATCH * SEQ * DIM];
__device__ uint32_t g_MB[SEQ * MBW];

// fast exp on the FMA pipe
__device__ __forceinline__ float fast_exp(float x) {
    float n = rintf(x * 1.4426950408889634f);
    float r = fmaf(n, -0.6931471805599453f, x);
    float e = fmaf(r, 8.3333337e-3f, 4.1666668e-2f);
    e = fmaf(r, e, 0.16666667f);
    e = fmaf(r, e, 0.5f);
    e = fmaf(r, e, 1.0f);
    e = fmaf(r, e, 1.0f);
    int ni = (int)n;
    return e * __int_as_float((ni + 127) << 23);
}

// ---------------------------------------------------------------------------
// mask (int32) -> bitmask words
// ---------------------------------------------------------------------------
__global__ __launch_bounds__(256)
void mask_bits_kernel(const int* __restrict__ mask)
{
    int idx = blockIdx.x * 256 + threadIdx.x;
    uint32_t bit = (mask[idx] != 0) ? 1u : 0u;
    uint32_t word = __ballot_sync(0xffffffffu, bit);
    if ((threadIdx.x & 31) == 0) g_MB[idx >> 5] = word;
}

// ---------------------------------------------------------------------------
// FP16 GEMM + bias (+out scale): C = (A @ W + bias) * scale
// A dtype TA (float or __half), out dtype OT (float or __half).
// 128x64x32 tile, double-buffered smem, 8 warps (4m x 2n), warp 32x32.
// mma.sync acc layout: x[g*4+{0,1}] -> (row lane>>2, cols g*8+2*(lane&3)+{0,1})
//                      x[g*4+{2,3}] -> (row lane>>2+8, same cols)
// ---------------------------------------------------------------------------
#define GBM 128
#define GBN 64
#define GBK 32
#define A_LDH 40
#define B_LDH 72

template <typename TA, typename OT>
__global__ __launch_bounds__(256, 2)
void gemm_fp16_bias(const TA* __restrict__ A0, const float* __restrict__ W0,
                    const float* __restrict__ bias0, OT* __restrict__ C0, float sc0,
                    const TA* __restrict__ A1, const float* __restrict__ W1,
                    const float* __restrict__ bias1, OT* __restrict__ C1, float sc1,
                    const TA* __restrict__ A2, const float* __restrict__ W2,
                    const float* __restrict__ bias2, OT* __restrict__ C2, float sc2,
                    int M, int N, int K)
{
    __shared__ __half As[2][GBM * A_LDH];
    __shared__ __half Bs[2][GBK * B_LDH];

    const int z = blockIdx.z;
    const TA*    A    = (z == 0) ? A0    : (z == 1) ? A1    : A2;
    const float* W    = (z == 0) ? W0    : (z == 1) ? W1    : W2;
    const float* bias = (z == 0) ? bias0 : (z == 1) ? bias1 : bias2;
    OT*          C    = (z == 0) ? C0    : (z == 1) ? C1    : C2;
    const float  sc   = (z == 0) ? sc0   : (z == 1) ? sc1   : sc2;

    const int tid  = threadIdx.x;
    const int lane = tid & 31;
    const int w    = tid >> 5;
    const int wm   = w >> 1;
    const int wn   = w & 1;
    const int row0 = blockIdx.y * GBM;
    const int col0 = blockIdx.x * GBN;

    wmma::fragment<wmma::accumulator, 16, 16, 16, float> acc[2][2];
#pragma unroll
    for (int mf = 0; mf < 2; mf++)
#pragma unroll
        for (int nf = 0; nf < 2; nf++)
            wmma::fill_fragment(acc[mf][nf], 0.f);

    // B load coords (fp32 weights): 2 float4 per thread
    int bk_[2], bn_[2];
#pragma unroll
    for (int it = 0; it < 2; it++) { int q = tid + it * 256; bk_[it] = q >> 4; bn_[it] = q & 15; }

    // A load/store helper
    auto stage_A = [&](int buf, int kt) {
        if constexpr (__is_same(TA, float)) {
#pragma unroll
            for (int it = 0; it < 4; it++) {
                int q = tid + it * 256;
                int r = q >> 3, kq = q & 7;
                float4 v = *reinterpret_cast<const float4*>(A + (size_t)(row0 + r) * K + kt + kq * 4);
                __half2* dst = reinterpret_cast<__half2*>(&As[buf][r * A_LDH + kq * 4]);
                dst[0] = __floats2half2_rn(v.x, v.y);
                dst[1] = __floats2half2_rn(v.z, v.w);
            }
        } else {
#pragma unroll
            for (int it = 0; it < 2; it++) {
                int q = tid + it * 256;
                int r = q >> 2, hq = q & 3;   // 4 uint4 per row of 32 halves
                uint4 v = *reinterpret_cast<const uint4*>(A + (size_t)(row0 + r) * K + kt + hq * 8);
                *reinterpret_cast<uint4*>(&As[buf][r * A_LDH + hq * 8]) = v;
            }
        }
    };
    auto stage_B = [&](int buf, const float4* pb) {
#pragma unroll
        for (int it = 0; it < 2; it++) {
            __half2* dst = reinterpret_cast<__half2*>(&Bs[buf][bk_[it] * B_LDH + bn_[it] * 4]);
            dst[0] = __floats2half2_rn(pb[it].x, pb[it].y);
            dst[1] = __floats2half2_rn(pb[it].z, pb[it].w);
        }
    };

    // prolog
    {
        float4 pb[2];
#pragma unroll
        for (int it = 0; it < 2; it++)
            pb[it] = *reinterpret_cast<const float4*>(W + (size_t)bk_[it] * N + col0 + bn_[it] * 4);
        stage_A(0, 0);
        stage_B(0, pb);
    }
    __syncthreads();

    int buf = 0;
    for (int kt = 0; kt < K; kt += GBK) {
        const bool has_next = (kt + GBK) < K;
        float4 pb[2];
        if (has_next) {
            const int kn = kt + GBK;
#pragma unroll
            for (int it = 0; it < 2; it++)
                pb[it] = *reinterpret_cast<const float4*>(W + (size_t)(kn + bk_[it]) * N + col0 + bn_[it] * 4);
        }

        const __half* sA = &As[buf][0];
        const __half* sB = &Bs[buf][0];
#pragma unroll
        for (int ks = 0; ks < 2; ks++) {
            const int k0 = ks * 16;
            wmma::fragment<wmma::matrix_a, 16, 16, 16, __half, wmma::row_major> af[2];
            wmma::fragment<wmma::matrix_b, 16, 16, 16, __half, wmma::row_major> bf[2];
#pragma unroll
            for (int mf = 0; mf < 2; mf++)
                wmma::load_matrix_sync(af[mf], &sA[(wm * 32 + mf * 16) * A_LDH + k0], A_LDH);
#pragma unroll
            for (int nf = 0; nf < 2; nf++)
                wmma::load_matrix_sync(bf[nf], &sB[k0 * B_LDH + wn * 32 + nf * 16], B_LDH);
#pragma unroll
            for (int mf = 0; mf < 2; mf++)
#pragma unroll
                for (int nf = 0; nf < 2; nf++)
                    wmma::mma_sync(acc[mf][nf], af[mf], bf[nf], acc[mf][nf]);
        }

        if (has_next) {
            stage_A(buf ^ 1, kt + GBK);
            stage_B(buf ^ 1, pb);
        }
        __syncthreads();
        buf ^= 1;
    }

    // epilogue: (acc + bias) * scale
    float2 bb[2][2];
#pragma unroll
    for (int nf = 0; nf < 2; nf++)
#pragma unroll
        for (int g = 0; g < 2; g++)
            bb[nf][g] = *reinterpret_cast<const float2*>(
                &bias[col0 + wn * 32 + nf * 16 + g * 8 + 2 * (lane & 3)]);

#pragma unroll
    for (int mf = 0; mf < 2; mf++) {
        const int r = row0 + wm * 32 + mf * 16 + (lane >> 2);
#pragma unroll
        for (int nf = 0; nf < 2; nf++) {
#pragma unroll
            for (int g = 0; g < 2; g++) {
                const int col = col0 + wn * 32 + nf * 16 + g * 8 + 2 * (lane & 3);
                float v0 = (acc[mf][nf].x[g * 4 + 0] + bb[nf][g].x) * sc;
                float v1 = (acc[mf][nf].x[g * 4 + 1] + bb[nf][g].y) * sc;
                float v2 = (acc[mf][nf].x[g * 4 + 2] + bb[nf][g].x) * sc;
                float v3 = (acc[mf][nf].x[g * 4 + 3] + bb[nf][g].y) * sc;
                if constexpr (__is_same(OT, float)) {
                    *reinterpret_cast<float2*>(&C[(size_t)r * N + col])       = make_float2(v0, v1);
                    *reinterpret_cast<float2*>(&C[(size_t)(r + 8) * N + col]) = make_float2(v2, v3);
                } else {
                    *reinterpret_cast<__half2*>(&C[(size_t)r * N + col])       = __floats2half2_rn(v0, v1);
                    *reinterpret_cast<__half2*>(&C[(size_t)(r + 8) * N + col]) = __floats2half2_rn(v2, v3);
                }
            }
        }
    }
}

// ---------------------------------------------------------------------------
// Masked attention, fp16 in/out, double-buffered KV smem with reg prefetch.
// Q-tile 128 x KV-tile 64; exp+mask in-register; O from fragments to half ctx.
// Block: 256 threads = 8 warps (2m x 4n).
// ---------------------------------------------------------------------------
#define TSM 128
#define TSN 64
#define PADP 72

__global__ __launch_bounds__(256, 2)
void attn_fp16(__half* __restrict__ Og)
{
    extern __shared__ char smraw[];
    __half* Qs = reinterpret_cast<__half*>(smraw);          // [128][72]
    __half* Ks = Qs + TSM * PADP;                           // [2][64][72]
    __half* Vs = Ks + 2 * TSN * PADP;                       // [2][64][72]
    __half* Ps = Vs + 2 * TSN * PADP;                       // [128][72]
    float*  Ls = reinterpret_cast<float*>(Ps + TSM * PADP); // [4][128]

    const int qt = blockIdx.x;
    const int h  = blockIdx.y;
    const int b  = blockIdx.z;
    const int s0 = qt * TSM;
    const int tid  = threadIdx.x;
    const int lane = tid & 31;
    const int w    = tid >> 5;
    const int wm   = w >> 2;   // 0..1 : 64 rows
    const int wn   = w & 3;    // 0..3 : 16 cols

    const __half* Qbase = g_Qh + ((size_t)b * SEQ + s0) * DIM + h * HD;
    const __half* Kbase = g_Kh + (size_t)b * SEQ * DIM + h * HD;
    const __half* Vbase = g_Vh + (size_t)b * SEQ * DIM + h * HD;

    // KV per-thread coords: 512 uint4 per tile, 2 per thread
    const int kr0 = tid >> 3, ku0 = tid & 7;
    const int kr1 = (tid + 256) >> 3, ku1 = (tid + 256) & 7;

    // load Q tile: 128x64 halves = 1024 uint4, 4/thread (scale pre-folded)
#pragma unroll
    for (int it = 0; it < 4; it++) {
        int lin = tid + it * 256;
        int row = lin >> 3, u = lin & 7;
        *reinterpret_cast<uint4*>(&Qs[row * PADP + u * 8]) =
            *reinterpret_cast<const uint4*>(Qbase + (size_t)row * DIM + u * 8);
    }

    // prolog: KV tile 0 into buffer 0
    {
        *reinterpret_cast<uint4*>(&Ks[kr0 * PADP + ku0 * 8]) =
            *reinterpret_cast<const uint4*>(Kbase + (size_t)kr0 * DIM + ku0 * 8);
        *reinterpret_cast<uint4*>(&Ks[kr1 * PADP + ku1 * 8]) =
            *reinterpret_cast<const uint4*>(Kbase + (size_t)kr1 * DIM + ku1 * 8);
        *reinterpret_cast<uint4*>(&Vs[kr0 * PADP + ku0 * 8]) =
            *reinterpret_cast<const uint4*>(Vbase + (size_t)kr0 * DIM + ku0 * 8);
        *reinterpret_cast<uint4*>(&Vs[kr1 * PADP + ku1 * 8]) =
            *reinterpret_cast<const uint4*>(Vbase + (size_t)kr1 * DIM + ku1 * 8);
    }
    __syncthreads();

    wmma::fragment<wmma::accumulator, 16, 16, 16, float> ofrag[4];
#pragma unroll
    for (int f = 0; f < 4; f++) wmma::fill_fragment(ofrag[f], 0.f);

    float lsum[4][2];
#pragma unroll
    for (int f = 0; f < 4; f++) { lsum[f][0] = 0.f; lsum[f][1] = 0.f; }

    const int wrow = s0 + wm * 64 + (lane >> 2);
    const int sh   = (wn & 1) * 16;

    int buf = 0;
    for (int kt = 0; kt < SEQ; kt += TSN) {
        const bool has_next = (kt + TSN) < SEQ;

        // prefetch next KV tile into registers (overlaps with S mma)
        uint4 pk0, pk1, pv0, pv1;
        if (has_next) {
            const int kn = kt + TSN;
            pk0 = *reinterpret_cast<const uint4*>(Kbase + (size_t)(kn + kr0) * DIM + ku0 * 8);
            pk1 = *reinterpret_cast<const uint4*>(Kbase + (size_t)(kn + kr1) * DIM + ku1 * 8);
            pv0 = *reinterpret_cast<const uint4*>(Vbase + (size_t)(kn + kr0) * DIM + ku0 * 8);
            pv1 = *reinterpret_cast<const uint4*>(Vbase + (size_t)(kn + kr1) * DIM + ku1 * 8);
        }

        // mask word prefetch
        const int colw = (kt + wn * 16) >> 5;
        uint32_t mw0[4], mw8[4];
#pragma unroll
        for (int f = 0; f < 4; f++) {
            mw0[f] = g_MB[(wrow + f * 16) * MBW + colw];
            mw8[f] = g_MB[(wrow + f * 16 + 8) * MBW + colw];
        }

        // ---- S = Qs @ Ks^T ----
        const __half* Kb = &Ks[buf * TSN * PADP];
        const __half* Vb = &Vs[buf * TSN * PADP];
        wmma::fragment<wmma::accumulator, 16, 16, 16, float> sfrag[4];
#pragma unroll
        for (int f = 0; f < 4; f++) wmma::fill_fragment(sfrag[f], 0.f);

#pragma unroll
        for (int d0 = 0; d0 < HD; d0 += 16) {
            wmma::fragment<wmma::matrix_b, 16, 16, 16, __half, wmma::col_major> bkf;
            wmma::load_matrix_sync(bkf, &Kb[(wn * 16) * PADP + d0], PADP);
#pragma unroll
            for (int f = 0; f < 4; f++) {
                wmma::fragment<wmma::matrix_a, 16, 16, 16, __half, wmma::row_major> aq;
                wmma::load_matrix_sync(aq, &Qs[(wm * 64 + f * 16) * PADP + d0], PADP);
                wmma::mma_sync(sfrag[f], aq, bkf, sfrag[f]);
            }
        }

        // ---- in-register masked exp + partial row sums; store P ----
#pragma unroll
        for (int f = 0; f < 4; f++) {
            uint32_t b0 = (mw0[f] >> sh) & 0xFFFFu;
            uint32_t b8 = (mw8[f] >> sh) & 0xFFFFu;
            float rs0 = 0.f, rs8 = 0.f;
            const int prow = wm * 64 + f * 16 + (lane >> 2);
#pragma unroll
            for (int g = 0; g < 2; g++) {
                const int cb = g * 8 + 2 * (lane & 3);
                float p0 = ((b0 >> cb)       & 1u) ? fast_exp(sfrag[f].x[g * 4 + 0]) : 0.f;
                float p1 = ((b0 >> (cb + 1)) & 1u) ? fast_exp(sfrag[f].x[g * 4 + 1]) : 0.f;
                float p2 = ((b8 >> cb)       & 1u) ? fast_exp(sfrag[f].x[g * 4 + 2]) : 0.f;
                float p3 = ((b8 >> (cb + 1)) & 1u) ? fast_exp(sfrag[f].x[g * 4 + 3]) : 0.f;
                rs0 += p0 + p1;
                rs8 += p2 + p3;
                const int col = wn * 16 + cb;
                *reinterpret_cast<__half2*>(&Ps[prow * PADP + col])       = __floats2half2_rn(p0, p1);
                *reinterpret_cast<__half2*>(&Ps[(prow + 8) * PADP + col]) = __floats2half2_rn(p2, p3);
            }
            rs0 += __shfl_xor_sync(0xffffffffu, rs0, 1);
            rs0 += __shfl_xor_sync(0xffffffffu, rs0, 2);
            rs8 += __shfl_xor_sync(0xffffffffu, rs8, 1);
            rs8 += __shfl_xor_sync(0xffffffffu, rs8, 2);
            lsum[f][0] += rs0;
            lsum[f][1] += rs8;
        }
        __syncthreads();   // P visible; all warps done reading Ks[buf]

        // ---- O += P @ V ----
#pragma unroll
        for (int t0 = 0; t0 < TSN; t0 += 16) {
            wmma::fragment<wmma::matrix_b, 16, 16, 16, __half, wmma::row_major> bvf;
            wmma::load_matrix_sync(bvf, &Vb[t0 * PADP + wn * 16], PADP);
#pragma unroll
            for (int f = 0; f < 4; f++) {
                wmma::fragment<wmma::matrix_a, 16, 16, 16, __half, wmma::row_major> ap;
                wmma::load_matrix_sync(ap, &Ps[(wm * 64 + f * 16) * PADP + t0], PADP);
                wmma::mma_sync(ofrag[f], ap, bvf, ofrag[f]);
            }
        }

        // stage prefetched KV into other buffer
        if (has_next) {
            __half* Kn = &Ks[(buf ^ 1) * TSN * PADP];
            __half* Vn = &Vs[(buf ^ 1) * TSN * PADP];
            *reinterpret_cast<uint4*>(&Kn[kr0 * PADP + ku0 * 8]) = pk0;
            *reinterpret_cast<uint4*>(&Kn[kr1 * PADP + ku1 * 8]) = pk1;
            *reinterpret_cast<uint4*>(&Vn[kr0 * PADP + ku0 * 8]) = pv0;
            *reinterpret_cast<uint4*>(&Vn[kr1 * PADP + ku1 * 8]) = pv1;
        }
        __syncthreads();   // next buffer ready; Ps free for next iter
        buf ^= 1;
    }

    // ---- publish l partials ----
    if ((lane & 3) == 0) {
#pragma unroll
        for (int f = 0; f < 4; f++) {
            Ls[wn * TSM + wm * 64 + f * 16 + (lane >> 2)]     = lsum[f][0];
            Ls[wn * TSM + wm * 64 + f * 16 + (lane >> 2) + 8] = lsum[f][1];
        }
    }
    __syncthreads();

    // ---- normalize, write half ctx directly from fragments ----
#pragma unroll
    for (int f = 0; f < 4; f++) {
        const int row  = wm * 64 + f * 16 + (lane >> 2);
        const float l0 = Ls[row] + Ls[TSM + row] + Ls[2 * TSM + row] + Ls[3 * TSM + row];
        const float l8 = Ls[row + 8] + Ls[TSM + row + 8] + Ls[2 * TSM + row + 8] + Ls[3 * TSM + row + 8];
        const float inv0 = 1.f / l0;
        const float inv8 = 1.f / l8;
        __half* o0 = Og + ((size_t)b * SEQ + s0 + row) * DIM + h * HD;
        __half* o8 = Og + ((size_t)b * SEQ + s0 + row + 8) * DIM + h * HD;
#pragma unroll
        for (int g = 0; g < 2; g++) {
            const int col = wn * 16 + g * 8 + 2 * (lane & 3);
            *reinterpret_cast<__half2*>(&o0[col]) =
                __floats2half2_rn(ofrag[f].x[g * 4 + 0] * inv0, ofrag[f].x[g * 4 + 1] * inv0);
            *reinterpret_cast<__half2*>(&o8[col]) =
                __floats2half2_rn(ofrag[f].x[g * 4 + 2] * inv8, ofrag[f].x[g * 4 + 3] * inv8);
        }
    }
}

// ---------------------------------------------------------------------------
// Launch
// ---------------------------------------------------------------------------
extern "C" void kernel_launch(void* const* d_in, const int* in_sizes, int n_in,
                              void* d_out, int out_size)
{
    const float* query = (const float*)d_in[0];
    const float* key   = (const float*)d_in[1];
    const float* value = (const float*)d_in[2];
    const int*   mask  = (const int*)  d_in[3];
    const float* Wq = (const float*)d_in[4];
    const float* bq = (const float*)d_in[5];
    const float* Wk = (const float*)d_in[6];
    const float* bk = (const float*)d_in[7];
    const float* Wv = (const float*)d_in[8];
    const float* bv = (const float*)d_in[9];
    const float* Wo = (const float*)d_in[10];
    const float* bo = (const float*)d_in[11];
    float* out = (float*)d_out;

    __half *pQ, *pK, *pV, *pC;
    cudaGetSymbolAddress((void**)&pQ, g_Qh);
    cudaGetSymbolAddress((void**)&pK, g_Kh);
    cudaGetSymbolAddress((void**)&pV, g_Vh);
    cudaGetSymbolAddress((void**)&pC, g_Ch);

    const int M = BATCH * SEQ;   // 4096
    const int N = DIM;
    const int K = DIM;

    mask_bits_kernel<<<SEQ * SEQ / 256, 256>>>(mask);

    // Fused QKV: fp32 A -> half out, ATT_SCALE folded into Q
    dim3 qkv_grid(N / GBN, M / GBM, 3);
    gemm_fp16_bias<float, __half><<<qkv_grid, 256>>>(
        query, Wq, bq, pQ, ATT_SCALE,
        key,   Wk, bk, pK, 1.0f,
        value, Wv, bv, pV, 1.0f, M, N, K);

    // Attention (half in/out, double-buffered KV)
    const int attn_smem = (TSM * PADP + 4 * TSN * PADP + TSM * PADP) * 2 + 4 * TSM * 4;  // 75776 B
    cudaFuncSetAttribute(attn_fp16, cudaFuncAttributeMaxDynamicSharedMemorySize, attn_smem);
    attn_fp16<<<dim3(SEQ / TSM, NH, BATCH), 256, attn_smem>>>(pC);

    // Output projection: half A -> fp32 out
    dim3 ogrid(N / GBN, M / GBM, 1);
    gemm_fp16_bias<__half, float><<<ogrid, 256>>>(
        pC, Wo, bo, out, 1.0f,
        pC, Wo, bo, out, 1.0f,
        pC, Wo, bo, out, 1.0f, M, N, K);
}

// round 9
// speedup vs baseline: 1.3317x; 1.3166x over previous
#include <cuda_runtime.h>
#include <cuda_fp16.h>
#include <mma.h>
#include <cstdint>
#include <cstddef>

using namespace nvcuda;

// Problem constants
#define BATCH 2
#define SEQ   2048
#define DIM   1024
#define NH    16
#define HD    64
#define ATT_SCALE 0.125f
#define MBW   (SEQ / 32)
#define MTOT  (BATCH * SEQ)   // 4096

// Scratch (all fp16 intermediates)
__device__ __half g_Xh[3 * MTOT * DIM];    // converted query,key,value
__device__ __half g_Wh[4 * DIM * DIM];     // converted Wq,Wk,Wv,Wo
__device__ __half g_QKVh[3 * MTOT * DIM];  // projected Q,K,V
__device__ __half g_Ch[MTOT * DIM];        // attention context
__device__ uint32_t g_MB[SEQ * MBW];       // mask bit words

// ---------------------------------------------------------------------------
// PTX helpers
// ---------------------------------------------------------------------------
__device__ __forceinline__ uint32_t smemu32(const void* p) {
    return (uint32_t)__cvta_generic_to_shared(p);
}
__device__ __forceinline__ void cp16(uint32_t saddr, const void* g) {
    asm volatile("cp.async.cg.shared.global [%0], [%1], 16;" :: "r"(saddr), "l"(g));
}
__device__ __forceinline__ void cp_commit() { asm volatile("cp.async.commit_group;"); }
__device__ __forceinline__ void cp_wait0()  { asm volatile("cp.async.wait_group 0;"); }

__device__ __forceinline__ void ldsm4(uint32_t* r, uint32_t a) {
    asm volatile("ldmatrix.sync.aligned.m8n8.x4.shared.b16 {%0,%1,%2,%3}, [%4];"
        : "=r"(r[0]), "=r"(r[1]), "=r"(r[2]), "=r"(r[3]) : "r"(a));
}
__device__ __forceinline__ void ldsm4t(uint32_t* r, uint32_t a) {
    asm volatile("ldmatrix.sync.aligned.m8n8.x4.trans.shared.b16 {%0,%1,%2,%3}, [%4];"
        : "=r"(r[0]), "=r"(r[1]), "=r"(r[2]), "=r"(r[3]) : "r"(a));
}
__device__ __forceinline__ void mma16816(float& c0, float& c1, float& c2, float& c3,
                                         uint32_t a0, uint32_t a1, uint32_t a2, uint32_t a3,
                                         uint32_t b0, uint32_t b1) {
    asm volatile("mma.sync.aligned.m16n8k16.row.col.f32.f16.f16.f32 "
                 "{%0,%1,%2,%3}, {%4,%5,%6,%7}, {%8,%9}, {%0,%1,%2,%3};"
                 : "+f"(c0), "+f"(c1), "+f"(c2), "+f"(c3)
                 : "r"(a0), "r"(a1), "r"(a2), "r"(a3), "r"(b0), "r"(b1));
}
__device__ __forceinline__ uint32_t pack_h2(float a, float b) {
    __half2 h = __floats2half2_rn(a, b);
    return *reinterpret_cast<uint32_t*>(&h);
}

// fast exp on the FMA pipe
__device__ __forceinline__ float fast_exp(float x) {
    float n = rintf(x * 1.4426950408889634f);
    float r = fmaf(n, -0.6931471805599453f, x);
    float e = fmaf(r, 8.3333337e-3f, 4.1666668e-2f);
    e = fmaf(r, e, 0.16666667f);
    e = fmaf(r, e, 0.5f);
    e = fmaf(r, e, 1.0f);
    e = fmaf(r, e, 1.0f);
    int ni = (int)n;
    return e * __int_as_float((ni + 127) << 23);
}

// ---------------------------------------------------------------------------
// Pre-pass kernels: mask bits + fp32->fp16 conversion
// ---------------------------------------------------------------------------
__global__ __launch_bounds__(256)
void mask_bits_kernel(const int* __restrict__ mask)
{
    int idx = blockIdx.x * 256 + threadIdx.x;
    uint32_t bit = (mask[idx] != 0) ? 1u : 0u;
    uint32_t word = __ballot_sync(0xffffffffu, bit);
    if ((threadIdx.x & 31) == 0) g_MB[idx >> 5] = word;
}

__global__ __launch_bounds__(256)
void cvt_inputs(const float* __restrict__ q, const float* __restrict__ k,
                const float* __restrict__ v)
{
    const float* src = (blockIdx.y == 0) ? q : (blockIdx.y == 1) ? k : v;
    __half* dst = g_Xh + (size_t)blockIdx.y * MTOT * DIM;
    int i = blockIdx.x * 256 + threadIdx.x;           // float4 index
    float4 x = reinterpret_cast<const float4*>(src)[i];
    __half2* d = reinterpret_cast<__half2*>(dst + (size_t)i * 4);
    d[0] = __floats2half2_rn(x.x, x.y);
    d[1] = __floats2half2_rn(x.z, x.w);
}

__global__ __launch_bounds__(256)
void cvt_weights(const float* __restrict__ w0, const float* __restrict__ w1,
                 const float* __restrict__ w2, const float* __restrict__ w3)
{
    const float* src = (blockIdx.y == 0) ? w0 : (blockIdx.y == 1) ? w1
                     : (blockIdx.y == 2) ? w2 : w3;
    __half* dst = g_Wh + (size_t)blockIdx.y * DIM * DIM;
    int i = blockIdx.x * 256 + threadIdx.x;
    float4 x = reinterpret_cast<const float4*>(src)[i];
    __half2* d = reinterpret_cast<__half2*>(dst + (size_t)i * 4);
    d[0] = __floats2half2_rn(x.x, x.y);
    d[1] = __floats2half2_rn(x.z, x.w);
}

// ---------------------------------------------------------------------------
// All-half GEMM + bias (+scale): C = (A @ W + bias) * scale
// 128x64x32 tile, cp.async double-buffered, 8 warps (4m x 2n), wmma 16x16x16.
// ---------------------------------------------------------------------------
#define GBM 128
#define GBN 64
#define GBK 32
#define A_LDH 40
#define B_LDH 72

template <typename OT>
__global__ __launch_bounds__(256, 2)
void gemm_h(const __half* __restrict__ Abase, size_t sA,
            const __half* __restrict__ Wbase, size_t sW,
            const float* __restrict__ b0, const float* __restrict__ b1,
            const float* __restrict__ b2,
            OT* __restrict__ Cbase, size_t sC,
            float sc0, float sc1, float sc2)
{
    __shared__ __half As[2][GBM * A_LDH];
    __shared__ __half Bs[2][GBK * B_LDH];

    const int z = blockIdx.z;
    const __half* A = Abase + (size_t)z * sA;
    const __half* W = Wbase + (size_t)z * sW;
    const float* bias = (z == 0) ? b0 : (z == 1) ? b1 : b2;
    OT* C = Cbase + (size_t)z * sC;
    const float sc = (z == 0) ? sc0 : (z == 1) ? sc1 : sc2;

    const int tid = threadIdx.x, lane = tid & 31, w = tid >> 5;
    const int wm = w >> 1, wn = w & 1;
    const int row0 = blockIdx.y * GBM, col0 = blockIdx.x * GBN;
    const int N = DIM, K = DIM;

    const int ar0 = tid >> 2, ah = tid & 3;      // A rows 0..63
    const int ar1 = ar0 + 64;                    // A rows 64..127
    const int br  = tid >> 3, bu = tid & 7;      // B rows 0..31

    wmma::fragment<wmma::accumulator, 16, 16, 16, float> acc[2][2];
#pragma unroll
    for (int mf = 0; mf < 2; mf++)
#pragma unroll
        for (int nf = 0; nf < 2; nf++)
            wmma::fill_fragment(acc[mf][nf], 0.f);

    auto stage = [&](int buf, int kt) {
        cp16(smemu32(&As[buf][ar0 * A_LDH + ah * 8]), A + (size_t)(row0 + ar0) * K + kt + ah * 8);
        cp16(smemu32(&As[buf][ar1 * A_LDH + ah * 8]), A + (size_t)(row0 + ar1) * K + kt + ah * 8);
        cp16(smemu32(&Bs[buf][br * B_LDH + bu * 8]),  W + (size_t)(kt + br) * N + col0 + bu * 8);
    };

    stage(0, 0);
    cp_commit();

    int buf = 0;
    for (int kt = 0; kt < K; kt += GBK) {
        cp_wait0();
        __syncthreads();
        if (kt + GBK < K) { stage(buf ^ 1, kt + GBK); cp_commit(); }

        const __half* sAp = &As[buf][0];
        const __half* sBp = &Bs[buf][0];
#pragma unroll
        for (int ks = 0; ks < 2; ks++) {
            const int k0 = ks * 16;
            wmma::fragment<wmma::matrix_a, 16, 16, 16, __half, wmma::row_major> af[2];
            wmma::fragment<wmma::matrix_b, 16, 16, 16, __half, wmma::row_major> bf[2];
#pragma unroll
            for (int mf = 0; mf < 2; mf++)
                wmma::load_matrix_sync(af[mf], &sAp[(wm * 32 + mf * 16) * A_LDH + k0], A_LDH);
#pragma unroll
            for (int nf = 0; nf < 2; nf++)
                wmma::load_matrix_sync(bf[nf], &sBp[k0 * B_LDH + wn * 32 + nf * 16], B_LDH);
#pragma unroll
            for (int mf = 0; mf < 2; mf++)
#pragma unroll
                for (int nf = 0; nf < 2; nf++)
                    wmma::mma_sync(acc[mf][nf], af[mf], bf[nf], acc[mf][nf]);
        }
        buf ^= 1;
    }

    // epilogue: (acc + bias) * scale (mma.sync acc layout, validated R6/R7)
    float2 bb[2][2];
#pragma unroll
    for (int nf = 0; nf < 2; nf++)
#pragma unroll
        for (int g = 0; g < 2; g++)
            bb[nf][g] = *reinterpret_cast<const float2*>(
                &bias[col0 + wn * 32 + nf * 16 + g * 8 + 2 * (lane & 3)]);

#pragma unroll
    for (int mf = 0; mf < 2; mf++) {
        const int r = row0 + wm * 32 + mf * 16 + (lane >> 2);
#pragma unroll
        for (int nf = 0; nf < 2; nf++) {
#pragma unroll
            for (int g = 0; g < 2; g++) {
                const int col = col0 + wn * 32 + nf * 16 + g * 8 + 2 * (lane & 3);
                float v0 = (acc[mf][nf].x[g * 4 + 0] + bb[nf][g].x) * sc;
                float v1 = (acc[mf][nf].x[g * 4 + 1] + bb[nf][g].y) * sc;
                float v2 = (acc[mf][nf].x[g * 4 + 2] + bb[nf][g].x) * sc;
                float v3 = (acc[mf][nf].x[g * 4 + 3] + bb[nf][g].y) * sc;
                if constexpr (__is_same(OT, float)) {
                    *reinterpret_cast<float2*>(&C[(size_t)r * N + col])       = make_float2(v0, v1);
                    *reinterpret_cast<float2*>(&C[(size_t)(r + 8) * N + col]) = make_float2(v2, v3);
                } else {
                    *reinterpret_cast<__half2*>(&C[(size_t)r * N + col])       = __floats2half2_rn(v0, v1);
                    *reinterpret_cast<__half2*>(&C[(size_t)(r + 8) * N + col]) = __floats2half2_rn(v2, v3);
                }
            }
        }
    }
}

// ---------------------------------------------------------------------------
// FA2-style masked attention on raw mma.m16n8k16.
// 8 warps, each owns 16 Q rows (128-row Q tile), KV tile 64, cp.async DB.
// P stays in registers (S-acc fragment == PV A fragment layout).
// ---------------------------------------------------------------------------
#define ALD 72

__global__ __launch_bounds__(256, 2)
void attn_mma(__half* __restrict__ Og)
{
    extern __shared__ __half sm[];
    __half* Qs = sm;                    // [128][72]
    __half* Ks = Qs + 128 * ALD;        // [2][64][72]
    __half* Vs = Ks + 2 * 64 * ALD;     // [2][64][72]

    const int qt = blockIdx.x, h = blockIdx.y, b = blockIdx.z;
    const int s0 = qt * 128;
    const int tid = threadIdx.x, lane = tid & 31, w = tid >> 5;
    const int grp = lane >> 2, tig = lane & 3;
    const int q0 = w * 16;

    const __half* Qb = g_QKVh + ((size_t)b * SEQ + s0) * DIM + h * HD;
    const __half* Kb = g_QKVh + (size_t)MTOT * DIM + (size_t)b * SEQ * DIM + h * HD;
    const __half* Vb = g_QKVh + 2 * (size_t)MTOT * DIM + (size_t)b * SEQ * DIM + h * HD;

    // stage Q tile (scale pre-folded in projection): 1024 uint4, 4/thread
#pragma unroll
    for (int it = 0; it < 4; it++) {
        int lin = tid + it * 256, r = lin >> 3, u = lin & 7;
        *reinterpret_cast<uint4*>(&Qs[r * ALD + u * 8]) =
            *reinterpret_cast<const uint4*>(Qb + (size_t)r * DIM + u * 8);
    }

    // cp.async KV staging: 512 chunks per matrix, 2/thread each
    const int kr0 = tid >> 3, ku = tid & 7, kr1 = kr0 + 32;
    auto stage_kv = [&](int buf, int kt) {
        __half* Kd = Ks + buf * 64 * ALD;
        __half* Vd = Vs + buf * 64 * ALD;
        cp16(smemu32(&Kd[kr0 * ALD + ku * 8]), Kb + (size_t)(kt + kr0) * DIM + ku * 8);
        cp16(smemu32(&Kd[kr1 * ALD + ku * 8]), Kb + (size_t)(kt + kr1) * DIM + ku * 8);
        cp16(smemu32(&Vd[kr0 * ALD + ku * 8]), Vb + (size_t)(kt + kr0) * DIM + ku * 8);
        cp16(smemu32(&Vd[kr1 * ALD + ku * 8]), Vb + (size_t)(kt + kr1) * DIM + ku * 8);
    };
    stage_kv(0, 0);
    cp_commit();
    __syncthreads();   // Qs visible for ldmatrix

    // persistent Q A-fragments: qa[d0/16] covers k=d0..d0+16 of rows q0..q0+16
    uint32_t qa[4][4];
#pragma unroll
    for (int di = 0; di < 4; di++) {
        uint32_t a = smemu32(&Qs[(q0 + (lane & 15)) * ALD + di * 16 + 8 * (lane >> 4)]);
        ldsm4(qa[di], a);
    }

    float o[8][4];
#pragma unroll
    for (int j = 0; j < 8; j++)
#pragma unroll
        for (int e = 0; e < 4; e++) o[j][e] = 0.f;
    float lsum0 = 0.f, lsum8 = 0.f;

    const int mrow0 = (s0 + q0 + grp) * MBW;

    int buf = 0;
    for (int kt = 0; kt < SEQ; kt += 64) {
        cp_wait0();
        __syncthreads();
        if (kt + 64 < SEQ) { stage_kv(buf ^ 1, kt + 64); cp_commit(); }

        const __half* Kt = Ks + buf * 64 * ALD;
        const __half* Vt = Vs + buf * 64 * ALD;

        // mask words for this warp's two row-halves
        const int wi = kt >> 5;
        uint32_t mlo0 = g_MB[mrow0 + wi],           mlo1 = g_MB[mrow0 + wi + 1];
        uint32_t mhi0 = g_MB[mrow0 + 8 * MBW + wi], mhi1 = g_MB[mrow0 + 8 * MBW + wi + 1];

        // ---- S = Q @ K^T : 16 x 64 strip per warp ----
        float s[8][4];
#pragma unroll
        for (int j = 0; j < 8; j++)
#pragma unroll
            for (int e = 0; e < 4; e++) s[j][e] = 0.f;

#pragma unroll
        for (int di = 0; di < 4; di++) {
            const int d0 = di * 16;
#pragma unroll
            for (int ti = 0; ti < 4; ti++) {
                const int t0 = ti * 16;
                uint32_t kb[4];
                uint32_t a = smemu32(&Kt[(t0 + (lane & 7) + 8 * (lane >> 4)) * ALD
                                         + d0 + 8 * ((lane >> 3) & 1)]);
                ldsm4(kb, a);
                const int j = 2 * ti;
                mma16816(s[j][0], s[j][1], s[j][2], s[j][3],
                         qa[di][0], qa[di][1], qa[di][2], qa[di][3], kb[0], kb[1]);
                mma16816(s[j + 1][0], s[j + 1][1], s[j + 1][2], s[j + 1][3],
                         qa[di][0], qa[di][1], qa[di][2], qa[di][3], kb[2], kb[3]);
            }
        }

        // ---- masked exp + row sums + pack P (all in registers) ----
        uint32_t ph[8][2];
        float rs0 = 0.f, rs8 = 0.f;
#pragma unroll
        for (int j = 0; j < 8; j++) {
            uint32_t wlo = (j < 4) ? mlo0 : mlo1;
            uint32_t whi = (j < 4) ? mhi0 : mhi1;
            const int bit = (8 * j + 2 * tig) & 31;
            float p0 = ((wlo >> bit) & 1u)       ? fast_exp(s[j][0]) : 0.f;
            float p1 = ((wlo >> (bit + 1)) & 1u) ? fast_exp(s[j][1]) : 0.f;
            float p2 = ((whi >> bit) & 1u)       ? fast_exp(s[j][2]) : 0.f;
            float p3 = ((whi >> (bit + 1)) & 1u) ? fast_exp(s[j][3]) : 0.f;
            rs0 += p0 + p1;
            rs8 += p2 + p3;
            ph[j][0] = pack_h2(p0, p1);
            ph[j][1] = pack_h2(p2, p3);
        }
        rs0 += __shfl_xor_sync(0xffffffffu, rs0, 1);
        rs0 += __shfl_xor_sync(0xffffffffu, rs0, 2);
        rs8 += __shfl_xor_sync(0xffffffffu, rs8, 1);
        rs8 += __shfl_xor_sync(0xffffffffu, rs8, 2);
        lsum0 += rs0;
        lsum8 += rs8;

        // ---- O += P @ V (P from registers, V via ldmatrix.trans) ----
#pragma unroll
        for (int ti = 0; ti < 4; ti++) {
            const int t0 = ti * 16, j = 2 * ti;
#pragma unroll
            for (int ni = 0; ni < 4; ni++) {
                const int n0 = ni * 16;
                uint32_t vb[4];
                uint32_t a = smemu32(&Vt[(t0 + (lane & 15)) * ALD + n0 + 8 * (lane >> 4)]);
                ldsm4t(vb, a);
                const int jo = 2 * ni;
                mma16816(o[jo][0], o[jo][1], o[jo][2], o[jo][3],
                         ph[j][0], ph[j][1], ph[j + 1][0], ph[j + 1][1], vb[0], vb[1]);
                mma16816(o[jo + 1][0], o[jo + 1][1], o[jo + 1][2], o[jo + 1][3],
                         ph[j][0], ph[j][1], ph[j + 1][0], ph[j + 1][1], vb[2], vb[3]);
            }
        }
        buf ^= 1;
    }

    // ---- normalize + write half ctx ----
    const float inv0 = 1.f / lsum0;
    const float inv8 = 1.f / lsum8;
    __half* O0 = Og + ((size_t)b * SEQ + s0 + q0 + grp) * DIM + h * HD;
    __half* O8 = O0 + 8 * (size_t)DIM;
#pragma unroll
    for (int j = 0; j < 8; j++) {
        const int col = 8 * j + 2 * tig;
        *reinterpret_cast<__half2*>(&O0[col]) = __floats2half2_rn(o[j][0] * inv0, o[j][1] * inv0);
        *reinterpret_cast<__half2*>(&O8[col]) = __floats2half2_rn(o[j][2] * inv8, o[j][3] * inv8);
    }
}

// ---------------------------------------------------------------------------
// Launch
// ---------------------------------------------------------------------------
extern "C" void kernel_launch(void* const* d_in, const int* in_sizes, int n_in,
                              void* d_out, int out_size)
{
    const float* query = (const float*)d_in[0];
    const float* key   = (const float*)d_in[1];
    const float* value = (const float*)d_in[2];
    const int*   mask  = (const int*)  d_in[3];
    const float* Wq = (const float*)d_in[4];
    const float* bq = (const float*)d_in[5];
    const float* Wk = (const float*)d_in[6];
    const float* bk = (const float*)d_in[7];
    const float* Wv = (const float*)d_in[8];
    const float* bv = (const float*)d_in[9];
    const float* Wo = (const float*)d_in[10];
    const float* bo = (const float*)d_in[11];
    float* out = (float*)d_out;

    __half *pXh, *pWh, *pQKV, *pC;
    cudaGetSymbolAddress((void**)&pXh,  g_Xh);
    cudaGetSymbolAddress((void**)&pWh,  g_Wh);
    cudaGetSymbolAddress((void**)&pQKV, g_QKVh);
    cudaGetSymbolAddress((void**)&pC,   g_Ch);

    // pre-passes
    mask_bits_kernel<<<SEQ * SEQ / 256, 256>>>(mask);
    cvt_inputs<<<dim3(MTOT * DIM / 4 / 256, 3), 256>>>(query, key, value);
    cvt_weights<<<dim3(DIM * DIM / 4 / 256, 4), 256>>>(Wq, Wk, Wv, Wo);

    // fused QKV projections (all-half), ATT_SCALE folded into Q
    dim3 qkv_grid(DIM / GBN, MTOT / GBM, 3);   // (16, 32, 3)
    gemm_h<__half><<<qkv_grid, 256>>>(
        pXh, (size_t)MTOT * DIM, pWh, (size_t)DIM * DIM,
        bq, bk, bv, pQKV, (size_t)MTOT * DIM,
        ATT_SCALE, 1.0f, 1.0f);

    // attention
    const int attn_smem = (128 + 4 * 64) * ALD * (int)sizeof(__half);  // 55296 B
    cudaFuncSetAttribute(attn_mma, cudaFuncAttributeMaxDynamicSharedMemorySize, attn_smem);
    attn_mma<<<dim3(SEQ / 128, NH, BATCH), 256, attn_smem>>>(pC);

    // output projection (half A -> fp32 out)
    dim3 ogrid(DIM / GBN, MTOT / GBM, 1);
    gemm_h<float><<<ogrid, 256>>>(
        pC, 0, pWh + 3 * (size_t)DIM * DIM, 0,
        bo, bo, bo, out, 0,
        1.0f, 1.0f, 1.0f);
}

// round 11
// speedup vs baseline: 1.3990x; 1.0505x over previous
#include <cuda_runtime.h>
#include <cuda_fp16.h>
#include <mma.h>
#include <cstdint>
#include <cstddef>

using namespace nvcuda;

// Problem constants
#define BATCH 2
#define SEQ   2048
#define DIM   1024
#define NH    16
#define HD    64
#define ATT_SCALE 0.125f
#define MBW   (SEQ / 32)
#define MTOT  (BATCH * SEQ)   // 4096

// Scratch (all fp16 intermediates)
__device__ __half g_Xh[3 * MTOT * DIM];    // converted query,key,value
__device__ __half g_Wh[4 * DIM * DIM];     // converted Wq,Wk,Wv,Wo
__device__ __half g_QKVh[3 * MTOT * DIM];  // projected Q,K,V
__device__ __half g_Ch[MTOT * DIM];        // attention context
__device__ uint32_t g_MB[SEQ * MBW];       // mask bit words

// ---------------------------------------------------------------------------
// PTX helpers
// ---------------------------------------------------------------------------
__device__ __forceinline__ uint32_t smemu32(const void* p) {
    return (uint32_t)__cvta_generic_to_shared(p);
}
__device__ __forceinline__ void cp16(uint32_t saddr, const void* g) {
    asm volatile("cp.async.cg.shared.global [%0], [%1], 16;" :: "r"(saddr), "l"(g));
}
__device__ __forceinline__ void cp_commit() { asm volatile("cp.async.commit_group;"); }
__device__ __forceinline__ void cp_wait1()  { asm volatile("cp.async.wait_group 1;"); }
__device__ __forceinline__ void cp_wait2()  { asm volatile("cp.async.wait_group 2;"); }

__device__ __forceinline__ void ldsm4(uint32_t* r, uint32_t a) {
    asm volatile("ldmatrix.sync.aligned.m8n8.x4.shared.b16 {%0,%1,%2,%3}, [%4];"
        : "=r"(r[0]), "=r"(r[1]), "=r"(r[2]), "=r"(r[3]) : "r"(a));
}
__device__ __forceinline__ void ldsm4t(uint32_t* r, uint32_t a) {
    asm volatile("ldmatrix.sync.aligned.m8n8.x4.trans.shared.b16 {%0,%1,%2,%3}, [%4];"
        : "=r"(r[0]), "=r"(r[1]), "=r"(r[2]), "=r"(r[3]) : "r"(a));
}
__device__ __forceinline__ void mma16816(float& c0, float& c1, float& c2, float& c3,
                                         uint32_t a0, uint32_t a1, uint32_t a2, uint32_t a3,
                                         uint32_t b0, uint32_t b1) {
    asm volatile("mma.sync.aligned.m16n8k16.row.col.f32.f16.f16.f32 "
                 "{%0,%1,%2,%3}, {%4,%5,%6,%7}, {%8,%9}, {%0,%1,%2,%3};"
                 : "+f"(c0), "+f"(c1), "+f"(c2), "+f"(c3)
                 : "r"(a0), "r"(a1), "r"(a2), "r"(a3), "r"(b0), "r"(b1));
}
__device__ __forceinline__ uint32_t pack_h2(float a, float b) {
    __half2 h = __floats2half2_rn(a, b);
    return *reinterpret_cast<uint32_t*>(&h);
}

// fast exp on the FMA pipe
__device__ __forceinline__ float fast_exp(float x) {
    float n = rintf(x * 1.4426950408889634f);
    float r = fmaf(n, -0.6931471805599453f, x);
    float e = fmaf(r, 8.3333337e-3f, 4.1666668e-2f);
    e = fmaf(r, e, 0.16666667f);
    e = fmaf(r, e, 0.5f);
    e = fmaf(r, e, 1.0f);
    e = fmaf(r, e, 1.0f);
    int ni = (int)n;
    return e * __int_as_float((ni + 127) << 23);
}

// ---------------------------------------------------------------------------
// Pre-pass kernels: mask bits + fp32->fp16 conversion
// ---------------------------------------------------------------------------
__global__ __launch_bounds__(256)
void mask_bits_kernel(const int* __restrict__ mask)
{
    int idx = blockIdx.x * 256 + threadIdx.x;
    uint32_t bit = (mask[idx] != 0) ? 1u : 0u;
    uint32_t word = __ballot_sync(0xffffffffu, bit);
    if ((threadIdx.x & 31) == 0) g_MB[idx >> 5] = word;
}

__global__ __launch_bounds__(256)
void cvt_inputs(const float* __restrict__ q, const float* __restrict__ k,
                const float* __restrict__ v)
{
    const float* src = (blockIdx.y == 0) ? q : (blockIdx.y == 1) ? k : v;
    __half* dst = g_Xh + (size_t)blockIdx.y * MTOT * DIM;
    int i = blockIdx.x * 256 + threadIdx.x;           // float4 index
    float4 x = reinterpret_cast<const float4*>(src)[i];
    __half2* d = reinterpret_cast<__half2*>(dst + (size_t)i * 4);
    d[0] = __floats2half2_rn(x.x, x.y);
    d[1] = __floats2half2_rn(x.z, x.w);
}

__global__ __launch_bounds__(256)
void cvt_weights(const float* __restrict__ w0, const float* __restrict__ w1,
                 const float* __restrict__ w2, const float* __restrict__ w3)
{
    const float* src = (blockIdx.y == 0) ? w0 : (blockIdx.y == 1) ? w1
                     : (blockIdx.y == 2) ? w2 : w3;
    __half* dst = g_Wh + (size_t)blockIdx.y * DIM * DIM;
    int i = blockIdx.x * 256 + threadIdx.x;
    float4 x = reinterpret_cast<const float4*>(src)[i];
    __half2* d = reinterpret_cast<__half2*>(dst + (size_t)i * 4);
    d[0] = __floats2half2_rn(x.x, x.y);
    d[1] = __floats2half2_rn(x.z, x.w);
}

// ---------------------------------------------------------------------------
// All-half GEMM + bias (+scale): C = (A @ W + bias) * scale
// 128x64x32 tile, 4-stage cp.async pipeline (wait_group 2 -> ~3 MMA phases of
// cover), 8 warps (4m x 2n), wmma 16x16x16.
// DYNAMIC smem (59392B > 48KB static limit -- the R10 compile-breaker).
// ---------------------------------------------------------------------------
#define GBM 128
#define GBN 64
#define GBK 32
#define A_LDH 40
#define B_LDH 72
#define GSTG 4
#define G_A_ELT (GBM * A_LDH)                 // 5120 halves per A stage
#define G_B_ELT (GBK * B_LDH)                 // 2304 halves per B stage
#define GEMM_SMEM ((GSTG * (G_A_ELT + G_B_ELT)) * 2)   // 59392 bytes

template <typename OT>
__global__ __launch_bounds__(256, 2)
void gemm_h(const __half* __restrict__ Abase, size_t sA,
            const __half* __restrict__ Wbase, size_t sW,
            const float* __restrict__ b0, const float* __restrict__ b1,
            const float* __restrict__ b2,
            OT* __restrict__ Cbase, size_t sC,
            float sc0, float sc1, float sc2)
{
    extern __shared__ __half gsm[];
    __half* As = gsm;                          // [GSTG][G_A_ELT]
    __half* Bs = gsm + GSTG * G_A_ELT;         // [GSTG][G_B_ELT]

    const int z = blockIdx.z;
    const __half* A = Abase + (size_t)z * sA;
    const __half* W = Wbase + (size_t)z * sW;
    const float* bias = (z == 0) ? b0 : (z == 1) ? b1 : b2;
    OT* C = Cbase + (size_t)z * sC;
    const float sc = (z == 0) ? sc0 : (z == 1) ? sc1 : sc2;

    const int tid = threadIdx.x, lane = tid & 31, w = tid >> 5;
    const int wm = w >> 1, wn = w & 1;
    const int row0 = blockIdx.y * GBM, col0 = blockIdx.x * GBN;
    const int N = DIM, K = DIM;

    const int ar0 = tid >> 2, ah = tid & 3;      // A rows 0..63
    const int ar1 = ar0 + 64;                    // A rows 64..127
    const int br  = tid >> 3, bu = tid & 7;      // B rows 0..31

    wmma::fragment<wmma::accumulator, 16, 16, 16, float> acc[2][2];
#pragma unroll
    for (int mf = 0; mf < 2; mf++)
#pragma unroll
        for (int nf = 0; nf < 2; nf++)
            wmma::fill_fragment(acc[mf][nf], 0.f);

    auto stage = [&](int buf, int kt) {
        __half* Ad = As + buf * G_A_ELT;
        __half* Bd = Bs + buf * G_B_ELT;
        cp16(smemu32(&Ad[ar0 * A_LDH + ah * 8]), A + (size_t)(row0 + ar0) * K + kt + ah * 8);
        cp16(smemu32(&Ad[ar1 * A_LDH + ah * 8]), A + (size_t)(row0 + ar1) * K + kt + ah * 8);
        cp16(smemu32(&Bd[br * B_LDH + bu * 8]),  W + (size_t)(kt + br) * N + col0 + bu * 8);
    };

    // prolog: fill 3 stages
#pragma unroll
    for (int s = 0; s < GSTG - 1; s++) {
        stage(s, s * GBK);
        cp_commit();
    }

    const int NIT = K / GBK;   // 32
    for (int i = 0; i < NIT; i++) {
        cp_wait2();            // oldest group (stage i) complete
        __syncthreads();
        if (i + GSTG - 1 < NIT) stage((i + GSTG - 1) % GSTG, (i + GSTG - 1) * GBK);
        cp_commit();           // uniform group numbering (possibly empty group)

        const __half* sAp = As + (i % GSTG) * G_A_ELT;
        const __half* sBp = Bs + (i % GSTG) * G_B_ELT;
#pragma unroll
        for (int ks = 0; ks < 2; ks++) {
            const int k0 = ks * 16;
            wmma::fragment<wmma::matrix_a, 16, 16, 16, __half, wmma::row_major> af[2];
            wmma::fragment<wmma::matrix_b, 16, 16, 16, __half, wmma::row_major> bf[2];
#pragma unroll
            for (int mf = 0; mf < 2; mf++)
                wmma::load_matrix_sync(af[mf], &sAp[(wm * 32 + mf * 16) * A_LDH + k0], A_LDH);
#pragma unroll
            for (int nf = 0; nf < 2; nf++)
                wmma::load_matrix_sync(bf[nf], &sBp[k0 * B_LDH + wn * 32 + nf * 16], B_LDH);
#pragma unroll
            for (int mf = 0; mf < 2; mf++)
#pragma unroll
                for (int nf = 0; nf < 2; nf++)
                    wmma::mma_sync(acc[mf][nf], af[mf], bf[nf], acc[mf][nf]);
        }
    }

    // epilogue: (acc + bias) * scale (mma.sync acc layout, validated R6/R7/R9)
    float2 bb[2][2];
#pragma unroll
    for (int nf = 0; nf < 2; nf++)
#pragma unroll
        for (int g = 0; g < 2; g++)
            bb[nf][g] = *reinterpret_cast<const float2*>(
                &bias[col0 + wn * 32 + nf * 16 + g * 8 + 2 * (lane & 3)]);

#pragma unroll
    for (int mf = 0; mf < 2; mf++) {
        const int r = row0 + wm * 32 + mf * 16 + (lane >> 2);
#pragma unroll
        for (int nf = 0; nf < 2; nf++) {
#pragma unroll
            for (int g = 0; g < 2; g++) {
                const int col = col0 + wn * 32 + nf * 16 + g * 8 + 2 * (lane & 3);
                float v0 = (acc[mf][nf].x[g * 4 + 0] + bb[nf][g].x) * sc;
                float v1 = (acc[mf][nf].x[g * 4 + 1] + bb[nf][g].y) * sc;
                float v2 = (acc[mf][nf].x[g * 4 + 2] + bb[nf][g].x) * sc;
                float v3 = (acc[mf][nf].x[g * 4 + 3] + bb[nf][g].y) * sc;
                if constexpr (__is_same(OT, float)) {
                    *reinterpret_cast<float2*>(&C[(size_t)r * N + col])       = make_float2(v0, v1);
                    *reinterpret_cast<float2*>(&C[(size_t)(r + 8) * N + col]) = make_float2(v2, v3);
                } else {
                    *reinterpret_cast<__half2*>(&C[(size_t)r * N + col])       = __floats2half2_rn(v0, v1);
                    *reinterpret_cast<__half2*>(&C[(size_t)(r + 8) * N + col]) = __floats2half2_rn(v2, v3);
                }
            }
        }
    }
}

// ---------------------------------------------------------------------------
// FA2-style masked attention on raw mma.m16n8k16.
// 8 warps x 16 Q rows (128-row Q tile), KV tile 64, 3-stage cp.async pipeline.
// P stays in registers (S-acc fragment == PV A fragment layout).
// ---------------------------------------------------------------------------
#define ALD 72
#define ASTG 3

__global__ __launch_bounds__(256, 2)
void attn_mma(__half* __restrict__ Og)
{
    extern __shared__ __half sm[];
    __half* Qs = sm;                    // [128][72]
    __half* Ks = Qs + 128 * ALD;        // [3][64][72]
    __half* Vs = Ks + ASTG * 64 * ALD;  // [3][64][72]

    const int qt = blockIdx.x, h = blockIdx.y, b = blockIdx.z;
    const int s0 = qt * 128;
    const int tid = threadIdx.x, lane = tid & 31, w = tid >> 5;
    const int grp = lane >> 2, tig = lane & 3;
    const int q0 = w * 16;

    const __half* Qb = g_QKVh + ((size_t)b * SEQ + s0) * DIM + h * HD;
    const __half* Kb = g_QKVh + (size_t)MTOT * DIM + (size_t)b * SEQ * DIM + h * HD;
    const __half* Vb = g_QKVh + 2 * (size_t)MTOT * DIM + (size_t)b * SEQ * DIM + h * HD;

    // stage Q tile (scale pre-folded in projection): 1024 uint4, 4/thread
#pragma unroll
    for (int it = 0; it < 4; it++) {
        int lin = tid + it * 256, r = lin >> 3, u = lin & 7;
        *reinterpret_cast<uint4*>(&Qs[r * ALD + u * 8]) =
            *reinterpret_cast<const uint4*>(Qb + (size_t)r * DIM + u * 8);
    }

    // cp.async KV staging: 512 chunks per matrix, 2/thread each
    const int kr0 = tid >> 3, ku = tid & 7, kr1 = kr0 + 32;
    auto stage_kv = [&](int buf, int kt) {
        __half* Kd = Ks + buf * 64 * ALD;
        __half* Vd = Vs + buf * 64 * ALD;
        cp16(smemu32(&Kd[kr0 * ALD + ku * 8]), Kb + (size_t)(kt + kr0) * DIM + ku * 8);
        cp16(smemu32(&Kd[kr1 * ALD + ku * 8]), Kb + (size_t)(kt + kr1) * DIM + ku * 8);
        cp16(smemu32(&Vd[kr0 * ALD + ku * 8]), Vb + (size_t)(kt + kr0) * DIM + ku * 8);
        cp16(smemu32(&Vd[kr1 * ALD + ku * 8]), Vb + (size_t)(kt + kr1) * DIM + ku * 8);
    };
    stage_kv(0, 0);
    cp_commit();
    stage_kv(1, 64);
    cp_commit();
    __syncthreads();   // Qs visible for ldmatrix

    // persistent Q A-fragments
    uint32_t qa[4][4];
#pragma unroll
    for (int di = 0; di < 4; di++) {
        uint32_t a = smemu32(&Qs[(q0 + (lane & 15)) * ALD + di * 16 + 8 * (lane >> 4)]);
        ldsm4(qa[di], a);
    }

    float o[8][4];
#pragma unroll
    for (int j = 0; j < 8; j++)
#pragma unroll
        for (int e = 0; e < 4; e++) o[j][e] = 0.f;
    float lsum0 = 0.f, lsum8 = 0.f;

    const int mrow0 = (s0 + q0 + grp) * MBW;

    const int NIT = SEQ / 64;   // 32
    for (int i = 0; i < NIT; i++) {
        cp_wait1();              // stage i complete (up to 1 newer pending)
        __syncthreads();
        if (i + 2 < NIT) stage_kv((i + 2) % ASTG, (i + 2) * 64);
        cp_commit();

        const __half* Kt = Ks + (i % ASTG) * 64 * ALD;
        const __half* Vt = Vs + (i % ASTG) * 64 * ALD;
        const int kt = i * 64;

        // mask words for this warp's two row-halves
        const int wi = kt >> 5;
        uint32_t mlo0 = g_MB[mrow0 + wi],           mlo1 = g_MB[mrow0 + wi + 1];
        uint32_t mhi0 = g_MB[mrow0 + 8 * MBW + wi], mhi1 = g_MB[mrow0 + 8 * MBW + wi + 1];

        // ---- S = Q @ K^T : 16 x 64 strip per warp ----
        float s[8][4];
#pragma unroll
        for (int j = 0; j < 8; j++)
#pragma unroll
            for (int e = 0; e < 4; e++) s[j][e] = 0.f;

#pragma unroll
        for (int di = 0; di < 4; di++) {
            const int d0 = di * 16;
#pragma unroll
            for (int ti = 0; ti < 4; ti++) {
                const int t0 = ti * 16;
                uint32_t kb[4];
                uint32_t a = smemu32(&Kt[(t0 + (lane & 7) + 8 * (lane >> 4)) * ALD
                                         + d0 + 8 * ((lane >> 3) & 1)]);
                ldsm4(kb, a);
                const int j = 2 * ti;
                mma16816(s[j][0], s[j][1], s[j][2], s[j][3],
                         qa[di][0], qa[di][1], qa[di][2], qa[di][3], kb[0], kb[1]);
                mma16816(s[j + 1][0], s[j + 1][1], s[j + 1][2], s[j + 1][3],
                         qa[di][0], qa[di][1], qa[di][2], qa[di][3], kb[2], kb[3]);
            }
        }

        // ---- masked exp + row sums + pack P (all in registers) ----
        uint32_t ph[8][2];
        float rs0 = 0.f, rs8 = 0.f;
#pragma unroll
        for (int j = 0; j < 8; j++) {
            uint32_t wlo = (j < 4) ? mlo0 : mlo1;
            uint32_t whi = (j < 4) ? mhi0 : mhi1;
            const int bit = (8 * j + 2 * tig) & 31;
            float p0 = ((wlo >> bit) & 1u)       ? fast_exp(s[j][0]) : 0.f;
            float p1 = ((wlo >> (bit + 1)) & 1u) ? fast_exp(s[j][1]) : 0.f;
            float p2 = ((whi >> bit) & 1u)       ? fast_exp(s[j][2]) : 0.f;
            float p3 = ((whi >> (bit + 1)) & 1u) ? fast_exp(s[j][3]) : 0.f;
            rs0 += p0 + p1;
            rs8 += p2 + p3;
            ph[j][0] = pack_h2(p0, p1);
            ph[j][1] = pack_h2(p2, p3);
        }
        rs0 += __shfl_xor_sync(0xffffffffu, rs0, 1);
        rs0 += __shfl_xor_sync(0xffffffffu, rs0, 2);
        rs8 += __shfl_xor_sync(0xffffffffu, rs8, 1);
        rs8 += __shfl_xor_sync(0xffffffffu, rs8, 2);
        lsum0 += rs0;
        lsum8 += rs8;

        // ---- O += P @ V (P from registers, V via ldmatrix.trans) ----
#pragma unroll
        for (int ti = 0; ti < 4; ti++) {
            const int t0 = ti * 16, j = 2 * ti;
#pragma unroll
            for (int ni = 0; ni < 4; ni++) {
                const int n0 = ni * 16;
                uint32_t vb[4];
                uint32_t a = smemu32(&Vt[(t0 + (lane & 15)) * ALD + n0 + 8 * (lane >> 4)]);
                ldsm4t(vb, a);
                const int jo = 2 * ni;
                mma16816(o[jo][0], o[jo][1], o[jo][2], o[jo][3],
                         ph[j][0], ph[j][1], ph[j + 1][0], ph[j + 1][1], vb[0], vb[1]);
                mma16816(o[jo + 1][0], o[jo + 1][1], o[jo + 1][2], o[jo + 1][3],
                         ph[j][0], ph[j][1], ph[j + 1][0], ph[j + 1][1], vb[2], vb[3]);
            }
        }
    }

    // ---- normalize + write half ctx ----
    const float inv0 = 1.f / lsum0;
    const float inv8 = 1.f / lsum8;
    __half* O0 = Og + ((size_t)b * SEQ + s0 + q0 + grp) * DIM + h * HD;
    __half* O8 = O0 + 8 * (size_t)DIM;
#pragma unroll
    for (int j = 0; j < 8; j++) {
        const int col = 8 * j + 2 * tig;
        *reinterpret_cast<__half2*>(&O0[col]) = __floats2half2_rn(o[j][0] * inv0, o[j][1] * inv0);
        *reinterpret_cast<__half2*>(&O8[col]) = __floats2half2_rn(o[j][2] * inv8, o[j][3] * inv8);
    }
}

// ---------------------------------------------------------------------------
// Launch
// ---------------------------------------------------------------------------
extern "C" void kernel_launch(void* const* d_in, const int* in_sizes, int n_in,
                              void* d_out, int out_size)
{
    const float* query = (const float*)d_in[0];
    const float* key   = (const float*)d_in[1];
    const float* value = (const float*)d_in[2];
    const int*   mask  = (const int*)  d_in[3];
    const float* Wq = (const float*)d_in[4];
    const float* bq = (const float*)d_in[5];
    const float* Wk = (const float*)d_in[6];
    const float* bk = (const float*)d_in[7];
    const float* Wv = (const float*)d_in[8];
    const float* bv = (const float*)d_in[9];
    const float* Wo = (const float*)d_in[10];
    const float* bo = (const float*)d_in[11];
    float* out = (float*)d_out;

    __half *pXh, *pWh, *pQKV, *pC;
    cudaGetSymbolAddress((void**)&pXh,  g_Xh);
    cudaGetSymbolAddress((void**)&pWh,  g_Wh);
    cudaGetSymbolAddress((void**)&pQKV, g_QKVh);
    cudaGetSymbolAddress((void**)&pC,   g_Ch);

    // pre-passes
    mask_bits_kernel<<<SEQ * SEQ / 256, 256>>>(mask);
    cvt_inputs<<<dim3(MTOT * DIM / 4 / 256, 3), 256>>>(query, key, value);
    cvt_weights<<<dim3(DIM * DIM / 4 / 256, 4), 256>>>(Wq, Wk, Wv, Wo);

    // fused QKV projections (all-half), ATT_SCALE folded into Q
    cudaFuncSetAttribute(gemm_h<__half>, cudaFuncAttributeMaxDynamicSharedMemorySize, GEMM_SMEM);
    cudaFuncSetAttribute(gemm_h<float>,  cudaFuncAttributeMaxDynamicSharedMemorySize, GEMM_SMEM);
    dim3 qkv_grid(DIM / GBN, MTOT / GBM, 3);   // (16, 32, 3)
    gemm_h<__half><<<qkv_grid, 256, GEMM_SMEM>>>(
        pXh, (size_t)MTOT * DIM, pWh, (size_t)DIM * DIM,
        bq, bk, bv, pQKV, (size_t)MTOT * DIM,
        ATT_SCALE, 1.0f, 1.0f);

    // attention (3-stage KV pipeline)
    const int attn_smem = (128 + 2 * ASTG * 64) * ALD * (int)sizeof(__half);  // 73728 B
    cudaFuncSetAttribute(attn_mma, cudaFuncAttributeMaxDynamicSharedMemorySize, attn_smem);
    attn_mma<<<dim3(SEQ / 128, NH, BATCH), 256, attn_smem>>>(pC);

    // output projection (half A -> fp32 out)
    dim3 ogrid(DIM / GBN, MTOT / GBM, 1);
    gemm_h<float><<<ogrid, 256, GEMM_SMEM>>>(
        pC, 0, pWh + 3 * (size_t)DIM * DIM, 0,
        bo, bo, bo, out, 0,
        1.0f, 1.0f, 1.0f);
}

// round 12
// speedup vs baseline: 1.4656x; 1.0476x over previous
#include <cuda_runtime.h>
#include <cuda_fp16.h>
#include <mma.h>
#include <cstdint>
#include <cstddef>

using namespace nvcuda;

// Problem constants
#define BATCH 2
#define SEQ   2048
#define DIM   1024
#define NH    16
#define HD    64
#define ATT_SCALE 0.125f
#define MBW   (SEQ / 32)
#define MTOT  (BATCH * SEQ)   // 4096

// Scratch (all fp16 intermediates)
__device__ __half g_Xh[3 * MTOT * DIM];    // converted query,key,value
__device__ __half g_Wh[4 * DIM * DIM];     // converted Wq,Wk,Wv,Wo
__device__ __half g_QKVh[3 * MTOT * DIM];  // projected Q,K,V
__device__ __half g_Ch[MTOT * DIM];        // attention context
__device__ uint32_t g_MB[SEQ * MBW];       // mask bit words

// ---------------------------------------------------------------------------
// PTX helpers
// ---------------------------------------------------------------------------
__device__ __forceinline__ uint32_t smemu32(const void* p) {
    return (uint32_t)__cvta_generic_to_shared(p);
}
__device__ __forceinline__ void cp16(uint32_t saddr, const void* g) {
    asm volatile("cp.async.cg.shared.global [%0], [%1], 16;" :: "r"(saddr), "l"(g));
}
__device__ __forceinline__ void cp_commit() { asm volatile("cp.async.commit_group;"); }
__device__ __forceinline__ void cp_wait1()  { asm volatile("cp.async.wait_group 1;"); }
__device__ __forceinline__ void cp_wait2()  { asm volatile("cp.async.wait_group 2;"); }

__device__ __forceinline__ void ldsm4(uint32_t* r, uint32_t a) {
    asm volatile("ldmatrix.sync.aligned.m8n8.x4.shared.b16 {%0,%1,%2,%3}, [%4];"
        : "=r"(r[0]), "=r"(r[1]), "=r"(r[2]), "=r"(r[3]) : "r"(a));
}
__device__ __forceinline__ void ldsm4t(uint32_t* r, uint32_t a) {
    asm volatile("ldmatrix.sync.aligned.m8n8.x4.trans.shared.b16 {%0,%1,%2,%3}, [%4];"
        : "=r"(r[0]), "=r"(r[1]), "=r"(r[2]), "=r"(r[3]) : "r"(a));
}
__device__ __forceinline__ void mma16816(float& c0, float& c1, float& c2, float& c3,
                                         uint32_t a0, uint32_t a1, uint32_t a2, uint32_t a3,
                                         uint32_t b0, uint32_t b1) {
    asm volatile("mma.sync.aligned.m16n8k16.row.col.f32.f16.f16.f32 "
                 "{%0,%1,%2,%3}, {%4,%5,%6,%7}, {%8,%9}, {%0,%1,%2,%3};"
                 : "+f"(c0), "+f"(c1), "+f"(c2), "+f"(c3)
                 : "r"(a0), "r"(a1), "r"(a2), "r"(a3), "r"(b0), "r"(b1));
}
__device__ __forceinline__ uint32_t pack_h2(float a, float b) {
    __half2 h = __floats2half2_rn(a, b);
    return *reinterpret_cast<uint32_t*>(&h);
}

// fast exp on the FMA pipe, magic-constant range reduction (no FRND/F2I).
// t = x*log2e + 1.5*2^23  ->  bits(t) = 0x4B400000 + round(x*log2e)
__device__ __forceinline__ float fast_exp(float x) {
    const float MAGIC = 12582912.0f;   // 1.5 * 2^23
    float t = fmaf(x, 1.4426950408889634f, MAGIC);
    int ni = __float_as_int(t);
    float n = t - MAGIC;
    float r = fmaf(n, -0.6931471805599453f, x);
    float e = fmaf(r, 4.1666668e-2f, 0.16666667f);   // deg-4 Taylor
    e = fmaf(r, e, 0.5f);
    e = fmaf(r, e, 1.0f);
    e = fmaf(r, e, 1.0f);
    float sc = __int_as_float((ni - 0x4B400000 + 127) << 23);
    return e * sc;
}

// ---------------------------------------------------------------------------
// Pre-pass kernels: mask bits + fp32->fp16 conversion
// ---------------------------------------------------------------------------
__global__ __launch_bounds__(256)
void mask_bits_kernel(const int* __restrict__ mask)
{
    int idx = blockIdx.x * 256 + threadIdx.x;
    uint32_t bit = (mask[idx] != 0) ? 1u : 0u;
    uint32_t word = __ballot_sync(0xffffffffu, bit);
    if ((threadIdx.x & 31) == 0) g_MB[idx >> 5] = word;
}

__global__ __launch_bounds__(256)
void cvt_inputs(const float* __restrict__ q, const float* __restrict__ k,
                const float* __restrict__ v)
{
    const float* src = (blockIdx.y == 0) ? q : (blockIdx.y == 1) ? k : v;
    __half* dst = g_Xh + (size_t)blockIdx.y * MTOT * DIM;
    int i = blockIdx.x * 256 + threadIdx.x;
    float4 x = reinterpret_cast<const float4*>(src)[i];
    __half2* d = reinterpret_cast<__half2*>(dst + (size_t)i * 4);
    d[0] = __floats2half2_rn(x.x, x.y);
    d[1] = __floats2half2_rn(x.z, x.w);
}

__global__ __launch_bounds__(256)
void cvt_weights(const float* __restrict__ w0, const float* __restrict__ w1,
                 const float* __restrict__ w2, const float* __restrict__ w3)
{
    const float* src = (blockIdx.y == 0) ? w0 : (blockIdx.y == 1) ? w1
                     : (blockIdx.y == 2) ? w2 : w3;
    __half* dst = g_Wh + (size_t)blockIdx.y * DIM * DIM;
    int i = blockIdx.x * 256 + threadIdx.x;
    float4 x = reinterpret_cast<const float4*>(src)[i];
    __half2* d = reinterpret_cast<__half2*>(dst + (size_t)i * 4);
    d[0] = __floats2half2_rn(x.x, x.y);
    d[1] = __floats2half2_rn(x.z, x.w);
}

// ---------------------------------------------------------------------------
// All-half GEMM + bias (+scale): C = (A @ W + bias) * scale
// 128x128x32 tile (2x arithmetic intensity vs R11's 128x64), 4-stage cp.async
// pipeline, 8 warps (2m x 4n), warp 64x32, wmma 16x16x16. Dynamic smem.
// ---------------------------------------------------------------------------
#define GBM 128
#define GBN 128
#define GBK 32
#define A_LDH 40
#define B_LDH 136
#define GSTG 4
#define G_A_ELT (GBM * A_LDH)                 // 5120 halves per A stage
#define G_B_ELT (GBK * B_LDH)                 // 4352 halves per B stage
#define GEMM_SMEM ((GSTG * (G_A_ELT + G_B_ELT)) * 2)   // 75776 bytes

template <typename OT>
__global__ __launch_bounds__(256, 2)
void gemm_h(const __half* __restrict__ Abase, size_t sA,
            const __half* __restrict__ Wbase, size_t sW,
            const float* __restrict__ b0, const float* __restrict__ b1,
            const float* __restrict__ b2,
            OT* __restrict__ Cbase, size_t sC,
            float sc0, float sc1, float sc2)
{
    extern __shared__ __half gsm[];
    __half* As = gsm;                          // [GSTG][G_A_ELT]
    __half* Bs = gsm + GSTG * G_A_ELT;         // [GSTG][G_B_ELT]

    const int z = blockIdx.z;
    const __half* A = Abase + (size_t)z * sA;
    const __half* W = Wbase + (size_t)z * sW;
    const float* bias = (z == 0) ? b0 : (z == 1) ? b1 : b2;
    OT* C = Cbase + (size_t)z * sC;
    const float sc = (z == 0) ? sc0 : (z == 1) ? sc1 : sc2;

    const int tid = threadIdx.x, lane = tid & 31, w = tid >> 5;
    const int wm = w >> 2, wn = w & 3;          // warp: rows wm*64, cols wn*32
    const int row0 = blockIdx.y * GBM, col0 = blockIdx.x * GBN;
    const int N = DIM, K = DIM;

    wmma::fragment<wmma::accumulator, 16, 16, 16, float> acc[4][2];
#pragma unroll
    for (int mf = 0; mf < 4; mf++)
#pragma unroll
        for (int nf = 0; nf < 2; nf++)
            wmma::fill_fragment(acc[mf][nf], 0.f);

    // staging coords: A 512 chunks (row=c>>2, cu=c&3), B 512 chunks (row=c>>4, cu=c&15)
    auto stage = [&](int buf, int kt) {
        __half* Ad = As + buf * G_A_ELT;
        __half* Bd = Bs + buf * G_B_ELT;
#pragma unroll
        for (int it = 0; it < 2; it++) {
            int c = tid + it * 256;
            int arow = c >> 2, acu = c & 3;
            cp16(smemu32(&Ad[arow * A_LDH + acu * 8]),
                 A + (size_t)(row0 + arow) * K + kt + acu * 8);
            int brow = c >> 4, bcu = c & 15;
            cp16(smemu32(&Bd[brow * B_LDH + bcu * 8]),
                 W + (size_t)(kt + brow) * N + col0 + bcu * 8);
        }
    };

    // prolog: fill 3 stages
#pragma unroll
    for (int s = 0; s < GSTG - 1; s++) {
        stage(s, s * GBK);
        cp_commit();
    }

    const int NIT = K / GBK;   // 32
    for (int i = 0; i < NIT; i++) {
        cp_wait2();            // oldest group complete
        __syncthreads();
        if (i + GSTG - 1 < NIT) stage((i + GSTG - 1) % GSTG, (i + GSTG - 1) * GBK);
        cp_commit();           // uniform group numbering

        const __half* sAp = As + (i % GSTG) * G_A_ELT;
        const __half* sBp = Bs + (i % GSTG) * G_B_ELT;
#pragma unroll
        for (int ks = 0; ks < 2; ks++) {
            const int k0 = ks * 16;
            wmma::fragment<wmma::matrix_a, 16, 16, 16, __half, wmma::row_major> af[4];
            wmma::fragment<wmma::matrix_b, 16, 16, 16, __half, wmma::row_major> bf[2];
#pragma unroll
            for (int mf = 0; mf < 4; mf++)
                wmma::load_matrix_sync(af[mf], &sAp[(wm * 64 + mf * 16) * A_LDH + k0], A_LDH);
#pragma unroll
            for (int nf = 0; nf < 2; nf++)
                wmma::load_matrix_sync(bf[nf], &sBp[k0 * B_LDH + wn * 32 + nf * 16], B_LDH);
#pragma unroll
            for (int mf = 0; mf < 4; mf++)
#pragma unroll
                for (int nf = 0; nf < 2; nf++)
                    wmma::mma_sync(acc[mf][nf], af[mf], bf[nf], acc[mf][nf]);
        }
    }

    // epilogue: (acc + bias) * scale (mma.sync acc layout, validated R6/R7/R9)
    float2 bb[2][2];
#pragma unroll
    for (int nf = 0; nf < 2; nf++)
#pragma unroll
        for (int g = 0; g < 2; g++)
            bb[nf][g] = *reinterpret_cast<const float2*>(
                &bias[col0 + wn * 32 + nf * 16 + g * 8 + 2 * (lane & 3)]);

#pragma unroll
    for (int mf = 0; mf < 4; mf++) {
        const int r = row0 + wm * 64 + mf * 16 + (lane >> 2);
#pragma unroll
        for (int nf = 0; nf < 2; nf++) {
#pragma unroll
            for (int g = 0; g < 2; g++) {
                const int col = col0 + wn * 32 + nf * 16 + g * 8 + 2 * (lane & 3);
                float v0 = (acc[mf][nf].x[g * 4 + 0] + bb[nf][g].x) * sc;
                float v1 = (acc[mf][nf].x[g * 4 + 1] + bb[nf][g].y) * sc;
                float v2 = (acc[mf][nf].x[g * 4 + 2] + bb[nf][g].x) * sc;
                float v3 = (acc[mf][nf].x[g * 4 + 3] + bb[nf][g].y) * sc;
                if constexpr (__is_same(OT, float)) {
                    *reinterpret_cast<float2*>(&C[(size_t)r * N + col])       = make_float2(v0, v1);
                    *reinterpret_cast<float2*>(&C[(size_t)(r + 8) * N + col]) = make_float2(v2, v3);
                } else {
                    *reinterpret_cast<__half2*>(&C[(size_t)r * N + col])       = __floats2half2_rn(v0, v1);
                    *reinterpret_cast<__half2*>(&C[(size_t)(r + 8) * N + col]) = __floats2half2_rn(v2, v3);
                }
            }
        }
    }
}

// ---------------------------------------------------------------------------
// FA2-style masked attention on raw mma.m16n8k16.
// 8 warps x 16 Q rows (128-row Q tile), KV tile 64, 3-stage cp.async pipeline.
// P stays in registers. K/V ldsm batched ahead of mma groups (latency cover).
// ---------------------------------------------------------------------------
#define ALD 72
#define ASTG 3

__global__ __launch_bounds__(256, 2)
void attn_mma(__half* __restrict__ Og)
{
    extern __shared__ __half sm[];
    __half* Qs = sm;                    // [128][72]
    __half* Ks = Qs + 128 * ALD;        // [3][64][72]
    __half* Vs = Ks + ASTG * 64 * ALD;  // [3][64][72]

    const int qt = blockIdx.x, h = blockIdx.y, b = blockIdx.z;
    const int s0 = qt * 128;
    const int tid = threadIdx.x, lane = tid & 31, w = tid >> 5;
    const int grp = lane >> 2, tig = lane & 3;
    const int q0 = w * 16;

    const __half* Qb = g_QKVh + ((size_t)b * SEQ + s0) * DIM + h * HD;
    const __half* Kb = g_QKVh + (size_t)MTOT * DIM + (size_t)b * SEQ * DIM + h * HD;
    const __half* Vb = g_QKVh + 2 * (size_t)MTOT * DIM + (size_t)b * SEQ * DIM + h * HD;

    // stage Q tile (scale pre-folded in projection): 1024 uint4, 4/thread
#pragma unroll
    for (int it = 0; it < 4; it++) {
        int lin = tid + it * 256, r = lin >> 3, u = lin & 7;
        *reinterpret_cast<uint4*>(&Qs[r * ALD + u * 8]) =
            *reinterpret_cast<const uint4*>(Qb + (size_t)r * DIM + u * 8);
    }

    // cp.async KV staging: 512 chunks per matrix, 2/thread each
    const int kr0 = tid >> 3, ku = tid & 7, kr1 = kr0 + 32;
    auto stage_kv = [&](int buf, int kt) {
        __half* Kd = Ks + buf * 64 * ALD;
        __half* Vd = Vs + buf * 64 * ALD;
        cp16(smemu32(&Kd[kr0 * ALD + ku * 8]), Kb + (size_t)(kt + kr0) * DIM + ku * 8);
        cp16(smemu32(&Kd[kr1 * ALD + ku * 8]), Kb + (size_t)(kt + kr1) * DIM + ku * 8);
        cp16(smemu32(&Vd[kr0 * ALD + ku * 8]), Vb + (size_t)(kt + kr0) * DIM + ku * 8);
        cp16(smemu32(&Vd[kr1 * ALD + ku * 8]), Vb + (size_t)(kt + kr1) * DIM + ku * 8);
    };
    stage_kv(0, 0);
    cp_commit();
    stage_kv(1, 64);
    cp_commit();
    __syncthreads();   // Qs visible for ldmatrix

    // persistent Q A-fragments
    uint32_t qa[4][4];
#pragma unroll
    for (int di = 0; di < 4; di++) {
        uint32_t a = smemu32(&Qs[(q0 + (lane & 15)) * ALD + di * 16 + 8 * (lane >> 4)]);
        ldsm4(qa[di], a);
    }

    float o[8][4];
#pragma unroll
    for (int j = 0; j < 8; j++)
#pragma unroll
        for (int e = 0; e < 4; e++) o[j][e] = 0.f;
    float lsum0 = 0.f, lsum8 = 0.f;

    const int mrow0 = (s0 + q0 + grp) * MBW;

    const int NIT = SEQ / 64;   // 32
    for (int i = 0; i < NIT; i++) {
        cp_wait1();              // stage i complete (up to 1 newer pending)
        __syncthreads();
        if (i + 2 < NIT) stage_kv((i + 2) % ASTG, (i + 2) * 64);
        cp_commit();

        const __half* Kt = Ks + (i % ASTG) * 64 * ALD;
        const __half* Vt = Vs + (i % ASTG) * 64 * ALD;
        const int kt = i * 64;

        // mask words for this warp's two row-halves
        const int wi = kt >> 5;
        uint32_t mlo0 = g_MB[mrow0 + wi],           mlo1 = g_MB[mrow0 + wi + 1];
        uint32_t mhi0 = g_MB[mrow0 + 8 * MBW + wi], mhi1 = g_MB[mrow0 + 8 * MBW + wi + 1];

        // ---- S = Q @ K^T : 16 x 64 strip per warp (ldsm batched per di) ----
        float s[8][4];
#pragma unroll
        for (int j = 0; j < 8; j++)
#pragma unroll
            for (int e = 0; e < 4; e++) s[j][e] = 0.f;

#pragma unroll
        for (int di = 0; di < 4; di++) {
            const int d0 = di * 16;
            uint32_t kb[4][4];
#pragma unroll
            for (int ti = 0; ti < 4; ti++) {
                uint32_t a = smemu32(&Kt[(ti * 16 + (lane & 7) + 8 * (lane >> 4)) * ALD
                                         + d0 + 8 * ((lane >> 3) & 1)]);
                ldsm4(kb[ti], a);
            }
#pragma unroll
            for (int ti = 0; ti < 4; ti++) {
                const int j = 2 * ti;
                mma16816(s[j][0], s[j][1], s[j][2], s[j][3],
                         qa[di][0], qa[di][1], qa[di][2], qa[di][3], kb[ti][0], kb[ti][1]);
                mma16816(s[j + 1][0], s[j + 1][1], s[j + 1][2], s[j + 1][3],
                         qa[di][0], qa[di][1], qa[di][2], qa[di][3], kb[ti][2], kb[ti][3]);
            }
        }

        // ---- masked exp + row sums + pack P (all in registers) ----
        uint32_t ph[8][2];
        float rs0 = 0.f, rs8 = 0.f;
#pragma unroll
        for (int j = 0; j < 8; j++) {
            uint32_t wlo = (j < 4) ? mlo0 : mlo1;
            uint32_t whi = (j < 4) ? mhi0 : mhi1;
            const int bit = (8 * j + 2 * tig) & 31;
            float p0 = ((wlo >> bit) & 1u)       ? fast_exp(s[j][0]) : 0.f;
            float p1 = ((wlo >> (bit + 1)) & 1u) ? fast_exp(s[j][1]) : 0.f;
            float p2 = ((whi >> bit) & 1u)       ? fast_exp(s[j][2]) : 0.f;
            float p3 = ((whi >> (bit + 1)) & 1u) ? fast_exp(s[j][3]) : 0.f;
            rs0 += p0 + p1;
            rs8 += p2 + p3;
            ph[j][0] = pack_h2(p0, p1);
            ph[j][1] = pack_h2(p2, p3);
        }
        rs0 += __shfl_xor_sync(0xffffffffu, rs0, 1);
        rs0 += __shfl_xor_sync(0xffffffffu, rs0, 2);
        rs8 += __shfl_xor_sync(0xffffffffu, rs8, 1);
        rs8 += __shfl_xor_sync(0xffffffffu, rs8, 2);
        lsum0 += rs0;
        lsum8 += rs8;

        // ---- O += P @ V (P from registers, V ldsm batched per ti) ----
#pragma unroll
        for (int ti = 0; ti < 4; ti++) {
            const int t0 = ti * 16, j = 2 * ti;
            uint32_t vb[4][4];
#pragma unroll
            for (int ni = 0; ni < 4; ni++) {
                uint32_t a = smemu32(&Vt[(t0 + (lane & 15)) * ALD + ni * 16 + 8 * (lane >> 4)]);
                ldsm4t(vb[ni], a);
            }
#pragma unroll
            for (int ni = 0; ni < 4; ni++) {
                const int jo = 2 * ni;
                mma16816(o[jo][0], o[jo][1], o[jo][2], o[jo][3],
                         ph[j][0], ph[j][1], ph[j + 1][0], ph[j + 1][1], vb[ni][0], vb[ni][1]);
                mma16816(o[jo + 1][0], o[jo + 1][1], o[jo + 1][2], o[jo + 1][3],
                         ph[j][0], ph[j][1], ph[j + 1][0], ph[j + 1][1], vb[ni][2], vb[ni][3]);
            }
        }
    }

    // ---- normalize + write half ctx ----
    const float inv0 = 1.f / lsum0;
    const float inv8 = 1.f / lsum8;
    __half* O0 = Og + ((size_t)b * SEQ + s0 + q0 + grp) * DIM + h * HD;
    __half* O8 = O0 + 8 * (size_t)DIM;
#pragma unroll
    for (int j = 0; j < 8; j++) {
        const int col = 8 * j + 2 * tig;
        *reinterpret_cast<__half2*>(&O0[col]) = __floats2half2_rn(o[j][0] * inv0, o[j][1] * inv0);
        *reinterpret_cast<__half2*>(&O8[col]) = __floats2half2_rn(o[j][2] * inv8, o[j][3] * inv8);
    }
}

// ---------------------------------------------------------------------------
// Launch
// ---------------------------------------------------------------------------
extern "C" void kernel_launch(void* const* d_in, const int* in_sizes, int n_in,
                              void* d_out, int out_size)
{
    const float* query = (const float*)d_in[0];
    const float* key   = (const float*)d_in[1];
    const float* value = (const float*)d_in[2];
    const int*   mask  = (const int*)  d_in[3];
    const float* Wq = (const float*)d_in[4];
    const float* bq = (const float*)d_in[5];
    const float* Wk = (const float*)d_in[6];
    const float* bk = (const float*)d_in[7];
    const float* Wv = (const float*)d_in[8];
    const float* bv = (const float*)d_in[9];
    const float* Wo = (const float*)d_in[10];
    const float* bo = (const float*)d_in[11];
    float* out = (float*)d_out;

    __half *pXh, *pWh, *pQKV, *pC;
    cudaGetSymbolAddress((void**)&pXh,  g_Xh);
    cudaGetSymbolAddress((void**)&pWh,  g_Wh);
    cudaGetSymbolAddress((void**)&pQKV, g_QKVh);
    cudaGetSymbolAddress((void**)&pC,   g_Ch);

    // pre-passes
    mask_bits_kernel<<<SEQ * SEQ / 256, 256>>>(mask);
    cvt_inputs<<<dim3(MTOT * DIM / 4 / 256, 3), 256>>>(query, key, value);
    cvt_weights<<<dim3(DIM * DIM / 4 / 256, 4), 256>>>(Wq, Wk, Wv, Wo);

    // fused QKV projections (all-half), ATT_SCALE folded into Q
    cudaFuncSetAttribute(gemm_h<__half>, cudaFuncAttributeMaxDynamicSharedMemorySize, GEMM_SMEM);
    cudaFuncSetAttribute(gemm_h<float>,  cudaFuncAttributeMaxDynamicSharedMemorySize, GEMM_SMEM);
    dim3 qkv_grid(DIM / GBN, MTOT / GBM, 3);   // (8, 32, 3)
    gemm_h<__half><<<qkv_grid, 256, GEMM_SMEM>>>(
        pXh, (size_t)MTOT * DIM, pWh, (size_t)DIM * DIM,
        bq, bk, bv, pQKV, (size_t)MTOT * DIM,
        ATT_SCALE, 1.0f, 1.0f);

    // attention (3-stage KV pipeline)
    const int attn_smem = (128 + 2 * ASTG * 64) * ALD * (int)sizeof(__half);  // 73728 B
    cudaFuncSetAttribute(attn_mma, cudaFuncAttributeMaxDynamicSharedMemorySize, attn_smem);
    attn_mma<<<dim3(SEQ / 128, NH, BATCH), 256, attn_smem>>>(pC);

    // output projection (half A -> fp32 out)
    dim3 ogrid(DIM / GBN, MTOT / GBM, 1);
    gemm_h<float><<<ogrid, 256, GEMM_SMEM>>>(
        pC, 0, pWh + 3 * (size_t)DIM * DIM, 0,
        bo, bo, bo, out, 0,
        1.0f, 1.0f, 1.0f);
}

// round 13
// speedup vs baseline: 1.7421x; 1.1887x over previous
#include <cuda_runtime.h>
#include <cuda_fp16.h>
#include <mma.h>
#include <cstdint>
#include <cstddef>

using namespace nvcuda;

// Problem constants
#define BATCH 2
#define SEQ   2048
#define DIM   1024
#define NH    16
#define HD    64
// ATT_SCALE * log2(e): S = (Q@K^T)*scale comes out in log2 domain -> exp = ex2
#define ATT_SCALE_LOG2E 0.1803368801111244f
#define MBW   (SEQ / 32)
#define MTOT  (BATCH * SEQ)   // 4096

// Scratch (all fp16 intermediates)
__device__ __half g_Xh[3 * MTOT * DIM];    // converted query,key,value
__device__ __half g_Wh[4 * DIM * DIM];     // converted Wq,Wk,Wv,Wo
__device__ __half g_QKVh[3 * MTOT * DIM];  // projected Q,K,V
__device__ __half g_Ch[MTOT * DIM];        // attention context
__device__ uint32_t g_MB[SEQ * MBW];       // mask bit words

// ---------------------------------------------------------------------------
// PTX helpers
// ---------------------------------------------------------------------------
__device__ __forceinline__ uint32_t smemu32(const void* p) {
    return (uint32_t)__cvta_generic_to_shared(p);
}
__device__ __forceinline__ void cp16(uint32_t saddr, const void* g) {
    asm volatile("cp.async.cg.shared.global [%0], [%1], 16;" :: "r"(saddr), "l"(g));
}
__device__ __forceinline__ void cp_commit() { asm volatile("cp.async.commit_group;"); }
__device__ __forceinline__ void cp_wait1()  { asm volatile("cp.async.wait_group 1;"); }
__device__ __forceinline__ void cp_wait2()  { asm volatile("cp.async.wait_group 2;"); }

__device__ __forceinline__ void ldsm4(uint32_t* r, uint32_t a) {
    asm volatile("ldmatrix.sync.aligned.m8n8.x4.shared.b16 {%0,%1,%2,%3}, [%4];"
        : "=r"(r[0]), "=r"(r[1]), "=r"(r[2]), "=r"(r[3]) : "r"(a));
}
__device__ __forceinline__ void ldsm4t(uint32_t* r, uint32_t a) {
    asm volatile("ldmatrix.sync.aligned.m8n8.x4.trans.shared.b16 {%0,%1,%2,%3}, [%4];"
        : "=r"(r[0]), "=r"(r[1]), "=r"(r[2]), "=r"(r[3]) : "r"(a));
}
__device__ __forceinline__ void mma16816(float& c0, float& c1, float& c2, float& c3,
                                         uint32_t a0, uint32_t a1, uint32_t a2, uint32_t a3,
                                         uint32_t b0, uint32_t b1) {
    asm volatile("mma.sync.aligned.m16n8k16.row.col.f32.f16.f16.f32 "
                 "{%0,%1,%2,%3}, {%4,%5,%6,%7}, {%8,%9}, {%0,%1,%2,%3};"
                 : "+f"(c0), "+f"(c1), "+f"(c2), "+f"(c3)
                 : "r"(a0), "r"(a1), "r"(a2), "r"(a3), "r"(b0), "r"(b1));
}
__device__ __forceinline__ uint32_t pack_h2(float a, float b) {
    __half2 h = __floats2half2_rn(a, b);
    return *reinterpret_cast<uint32_t*>(&h);
}
// 2^x on the MUFU pipe (input already in log2 domain)
__device__ __forceinline__ float ex2f(float x) {
    float y;
    asm("ex2.approx.f32 %0, %1;" : "=f"(y) : "f"(x));
    return y;
}

// ---------------------------------------------------------------------------
// Pre-pass kernels: mask bits + fp32->fp16 conversion
// ---------------------------------------------------------------------------
__global__ __launch_bounds__(256)
void mask_bits_kernel(const int* __restrict__ mask)
{
    int idx = blockIdx.x * 256 + threadIdx.x;
    uint32_t bit = (mask[idx] != 0) ? 1u : 0u;
    uint32_t word = __ballot_sync(0xffffffffu, bit);
    if ((threadIdx.x & 31) == 0) g_MB[idx >> 5] = word;
}

__global__ __launch_bounds__(256)
void cvt_inputs(const float* __restrict__ q, const float* __restrict__ k,
                const float* __restrict__ v)
{
    const float* src = (blockIdx.y == 0) ? q : (blockIdx.y == 1) ? k : v;
    __half* dst = g_Xh + (size_t)blockIdx.y * MTOT * DIM;
    int i = blockIdx.x * 256 + threadIdx.x;
    float4 x = reinterpret_cast<const float4*>(src)[i];
    __half2* d = reinterpret_cast<__half2*>(dst + (size_t)i * 4);
    d[0] = __floats2half2_rn(x.x, x.y);
    d[1] = __floats2half2_rn(x.z, x.w);
}

__global__ __launch_bounds__(256)
void cvt_weights(const float* __restrict__ w0, const float* __restrict__ w1,
                 const float* __restrict__ w2, const float* __restrict__ w3)
{
    const float* src = (blockIdx.y == 0) ? w0 : (blockIdx.y == 1) ? w1
                     : (blockIdx.y == 2) ? w2 : w3;
    __half* dst = g_Wh + (size_t)blockIdx.y * DIM * DIM;
    int i = blockIdx.x * 256 + threadIdx.x;
    float4 x = reinterpret_cast<const float4*>(src)[i];
    __half2* d = reinterpret_cast<__half2*>(dst + (size_t)i * 4);
    d[0] = __floats2half2_rn(x.x, x.y);
    d[1] = __floats2half2_rn(x.z, x.w);
}

// ---------------------------------------------------------------------------
// All-half GEMM + bias (+scale): C = (A @ W + bias) * scale
// 128x128x32 tile, 4-stage cp.async pipeline, 8 warps (2m x 4n), warp 64x32.
// ---------------------------------------------------------------------------
#define GBM 128
#define GBN 128
#define GBK 32
#define A_LDH 40
#define B_LDH 136
#define GSTG 4
#define G_A_ELT (GBM * A_LDH)                 // 5120 halves per A stage
#define G_B_ELT (GBK * B_LDH)                 // 4352 halves per B stage
#define GEMM_SMEM ((GSTG * (G_A_ELT + G_B_ELT)) * 2)   // 75776 bytes

template <typename OT>
__global__ __launch_bounds__(256, 2)
void gemm_h(const __half* __restrict__ Abase, size_t sA,
            const __half* __restrict__ Wbase, size_t sW,
            const float* __restrict__ b0, const float* __restrict__ b1,
            const float* __restrict__ b2,
            OT* __restrict__ Cbase, size_t sC,
            float sc0, float sc1, float sc2)
{
    extern __shared__ __half gsm[];
    __half* As = gsm;                          // [GSTG][G_A_ELT]
    __half* Bs = gsm + GSTG * G_A_ELT;         // [GSTG][G_B_ELT]

    const int z = blockIdx.z;
    const __half* A = Abase + (size_t)z * sA;
    const __half* W = Wbase + (size_t)z * sW;
    const float* bias = (z == 0) ? b0 : (z == 1) ? b1 : b2;
    OT* C = Cbase + (size_t)z * sC;
    const float sc = (z == 0) ? sc0 : (z == 1) ? sc1 : sc2;

    const int tid = threadIdx.x, lane = tid & 31, w = tid >> 5;
    const int wm = w >> 2, wn = w & 3;          // warp: rows wm*64, cols wn*32
    const int row0 = blockIdx.y * GBM, col0 = blockIdx.x * GBN;
    const int N = DIM, K = DIM;

    wmma::fragment<wmma::accumulator, 16, 16, 16, float> acc[4][2];
#pragma unroll
    for (int mf = 0; mf < 4; mf++)
#pragma unroll
        for (int nf = 0; nf < 2; nf++)
            wmma::fill_fragment(acc[mf][nf], 0.f);

    auto stage = [&](int buf, int kt) {
        __half* Ad = As + buf * G_A_ELT;
        __half* Bd = Bs + buf * G_B_ELT;
#pragma unroll
        for (int it = 0; it < 2; it++) {
            int c = tid + it * 256;
            int arow = c >> 2, acu = c & 3;
            cp16(smemu32(&Ad[arow * A_LDH + acu * 8]),
                 A + (size_t)(row0 + arow) * K + kt + acu * 8);
            int brow = c >> 4, bcu = c & 15;
            cp16(smemu32(&Bd[brow * B_LDH + bcu * 8]),
                 W + (size_t)(kt + brow) * N + col0 + bcu * 8);
        }
    };

    // prolog: fill 3 stages
#pragma unroll
    for (int s = 0; s < GSTG - 1; s++) {
        stage(s, s * GBK);
        cp_commit();
    }

    const int NIT = K / GBK;   // 32
    for (int i = 0; i < NIT; i++) {
        cp_wait2();
        __syncthreads();
        if (i + GSTG - 1 < NIT) stage((i + GSTG - 1) % GSTG, (i + GSTG - 1) * GBK);
        cp_commit();

        const __half* sAp = As + (i % GSTG) * G_A_ELT;
        const __half* sBp = Bs + (i % GSTG) * G_B_ELT;
#pragma unroll
        for (int ks = 0; ks < 2; ks++) {
            const int k0 = ks * 16;
            wmma::fragment<wmma::matrix_a, 16, 16, 16, __half, wmma::row_major> af[4];
            wmma::fragment<wmma::matrix_b, 16, 16, 16, __half, wmma::row_major> bf[2];
#pragma unroll
            for (int mf = 0; mf < 4; mf++)
                wmma::load_matrix_sync(af[mf], &sAp[(wm * 64 + mf * 16) * A_LDH + k0], A_LDH);
#pragma unroll
            for (int nf = 0; nf < 2; nf++)
                wmma::load_matrix_sync(bf[nf], &sBp[k0 * B_LDH + wn * 32 + nf * 16], B_LDH);
#pragma unroll
            for (int mf = 0; mf < 4; mf++)
#pragma unroll
                for (int nf = 0; nf < 2; nf++)
                    wmma::mma_sync(acc[mf][nf], af[mf], bf[nf], acc[mf][nf]);
        }
    }

    // epilogue: (acc + bias) * scale
    float2 bb[2][2];
#pragma unroll
    for (int nf = 0; nf < 2; nf++)
#pragma unroll
        for (int g = 0; g < 2; g++)
            bb[nf][g] = *reinterpret_cast<const float2*>(
                &bias[col0 + wn * 32 + nf * 16 + g * 8 + 2 * (lane & 3)]);

#pragma unroll
    for (int mf = 0; mf < 4; mf++) {
        const int r = row0 + wm * 64 + mf * 16 + (lane >> 2);
#pragma unroll
        for (int nf = 0; nf < 2; nf++) {
#pragma unroll
            for (int g = 0; g < 2; g++) {
                const int col = col0 + wn * 32 + nf * 16 + g * 8 + 2 * (lane & 3);
                float v0 = (acc[mf][nf].x[g * 4 + 0] + bb[nf][g].x) * sc;
                float v1 = (acc[mf][nf].x[g * 4 + 1] + bb[nf][g].y) * sc;
                float v2 = (acc[mf][nf].x[g * 4 + 2] + bb[nf][g].x) * sc;
                float v3 = (acc[mf][nf].x[g * 4 + 3] + bb[nf][g].y) * sc;
                if constexpr (__is_same(OT, float)) {
                    *reinterpret_cast<float2*>(&C[(size_t)r * N + col])       = make_float2(v0, v1);
                    *reinterpret_cast<float2*>(&C[(size_t)(r + 8) * N + col]) = make_float2(v2, v3);
                } else {
                    *reinterpret_cast<__half2*>(&C[(size_t)r * N + col])       = __floats2half2_rn(v0, v1);
                    *reinterpret_cast<__half2*>(&C[(size_t)(r + 8) * N + col]) = __floats2half2_rn(v2, v3);
                }
            }
        }
    }
}

// ---------------------------------------------------------------------------
// FA2-style masked attention on raw mma.m16n8k16.
// 8 warps x 16 Q rows (128-row Q tile), KV tile 64, 3-stage cp.async pipeline.
// S arrives in the log2 domain (log2e folded into Q scale) -> softmax
// numerator is ONE MUFU ex2 per value. Row-sum shuffles hoisted out of loop.
// ---------------------------------------------------------------------------
#define ALD 72
#define ASTG 3

__global__ __launch_bounds__(256, 2)
void attn_mma(__half* __restrict__ Og)
{
    extern __shared__ __half sm[];
    __half* Qs = sm;                    // [128][72]
    __half* Ks = Qs + 128 * ALD;        // [3][64][72]
    __half* Vs = Ks + ASTG * 64 * ALD;  // [3][64][72]

    const int qt = blockIdx.x, h = blockIdx.y, b = blockIdx.z;
    const int s0 = qt * 128;
    const int tid = threadIdx.x, lane = tid & 31, w = tid >> 5;
    const int grp = lane >> 2, tig = lane & 3;
    const int q0 = w * 16;

    const __half* Qb = g_QKVh + ((size_t)b * SEQ + s0) * DIM + h * HD;
    const __half* Kb = g_QKVh + (size_t)MTOT * DIM + (size_t)b * SEQ * DIM + h * HD;
    const __half* Vb = g_QKVh + 2 * (size_t)MTOT * DIM + (size_t)b * SEQ * DIM + h * HD;

    // stage Q tile (log2-domain scale pre-folded): 1024 uint4, 4/thread
#pragma unroll
    for (int it = 0; it < 4; it++) {
        int lin = tid + it * 256, r = lin >> 3, u = lin & 7;
        *reinterpret_cast<uint4*>(&Qs[r * ALD + u * 8]) =
            *reinterpret_cast<const uint4*>(Qb + (size_t)r * DIM + u * 8);
    }

    // cp.async KV staging: 512 chunks per matrix, 2/thread each
    const int kr0 = tid >> 3, ku = tid & 7, kr1 = kr0 + 32;
    auto stage_kv = [&](int buf, int kt) {
        __half* Kd = Ks + buf * 64 * ALD;
        __half* Vd = Vs + buf * 64 * ALD;
        cp16(smemu32(&Kd[kr0 * ALD + ku * 8]), Kb + (size_t)(kt + kr0) * DIM + ku * 8);
        cp16(smemu32(&Kd[kr1 * ALD + ku * 8]), Kb + (size_t)(kt + kr1) * DIM + ku * 8);
        cp16(smemu32(&Vd[kr0 * ALD + ku * 8]), Vb + (size_t)(kt + kr0) * DIM + ku * 8);
        cp16(smemu32(&Vd[kr1 * ALD + ku * 8]), Vb + (size_t)(kt + kr1) * DIM + ku * 8);
    };
    stage_kv(0, 0);
    cp_commit();
    stage_kv(1, 64);
    cp_commit();
    __syncthreads();   // Qs visible for ldmatrix

    // persistent Q A-fragments
    uint32_t qa[4][4];
#pragma unroll
    for (int di = 0; di < 4; di++) {
        uint32_t a = smemu32(&Qs[(q0 + (lane & 15)) * ALD + di * 16 + 8 * (lane >> 4)]);
        ldsm4(qa[di], a);
    }

    float o[8][4];
#pragma unroll
    for (int j = 0; j < 8; j++)
#pragma unroll
        for (int e = 0; e < 4; e++) o[j][e] = 0.f;
    float lsum0 = 0.f, lsum8 = 0.f;    // per-thread partials; reduced after loop

    const int mrow0 = (s0 + q0 + grp) * MBW;

    const int NIT = SEQ / 64;   // 32
    for (int i = 0; i < NIT; i++) {
        cp_wait1();
        __syncthreads();
        if (i + 2 < NIT) stage_kv((i + 2) % ASTG, (i + 2) * 64);
        cp_commit();

        const __half* Kt = Ks + (i % ASTG) * 64 * ALD;
        const __half* Vt = Vs + (i % ASTG) * 64 * ALD;
        const int kt = i * 64;

        // mask words for this warp's two row-halves
        const int wi = kt >> 5;
        uint32_t mlo0 = g_MB[mrow0 + wi],           mlo1 = g_MB[mrow0 + wi + 1];
        uint32_t mhi0 = g_MB[mrow0 + 8 * MBW + wi], mhi1 = g_MB[mrow0 + 8 * MBW + wi + 1];

        // ---- S = Q @ K^T (log2 domain) : 16 x 64 strip per warp ----
        float s[8][4];
#pragma unroll
        for (int j = 0; j < 8; j++)
#pragma unroll
            for (int e = 0; e < 4; e++) s[j][e] = 0.f;

#pragma unroll
        for (int di = 0; di < 4; di++) {
            const int d0 = di * 16;
            uint32_t kb[4][4];
#pragma unroll
            for (int ti = 0; ti < 4; ti++) {
                uint32_t a = smemu32(&Kt[(ti * 16 + (lane & 7) + 8 * (lane >> 4)) * ALD
                                         + d0 + 8 * ((lane >> 3) & 1)]);
                ldsm4(kb[ti], a);
            }
#pragma unroll
            for (int ti = 0; ti < 4; ti++) {
                const int j = 2 * ti;
                mma16816(s[j][0], s[j][1], s[j][2], s[j][3],
                         qa[di][0], qa[di][1], qa[di][2], qa[di][3], kb[ti][0], kb[ti][1]);
                mma16816(s[j + 1][0], s[j + 1][1], s[j + 1][2], s[j + 1][3],
                         qa[di][0], qa[di][1], qa[di][2], qa[di][3], kb[ti][2], kb[ti][3]);
            }
        }

        // ---- masked ex2 + row-sum partials + pack P (registers only) ----
        uint32_t ph[8][2];
#pragma unroll
        for (int j = 0; j < 8; j++) {
            uint32_t wlo = (j < 4) ? mlo0 : mlo1;
            uint32_t whi = (j < 4) ? mhi0 : mhi1;
            const int bit = (8 * j + 2 * tig) & 31;
            float p0 = ((wlo >> bit) & 1u)       ? ex2f(s[j][0]) : 0.f;
            float p1 = ((wlo >> (bit + 1)) & 1u) ? ex2f(s[j][1]) : 0.f;
            float p2 = ((whi >> bit) & 1u)       ? ex2f(s[j][2]) : 0.f;
            float p3 = ((whi >> (bit + 1)) & 1u) ? ex2f(s[j][3]) : 0.f;
            lsum0 += p0 + p1;
            lsum8 += p2 + p3;
            ph[j][0] = pack_h2(p0, p1);
            ph[j][1] = pack_h2(p2, p3);
        }

        // ---- O += P @ V (P from registers, V ldsm batched per ti) ----
#pragma unroll
        for (int ti = 0; ti < 4; ti++) {
            const int t0 = ti * 16, j = 2 * ti;
            uint32_t vb[4][4];
#pragma unroll
            for (int ni = 0; ni < 4; ni++) {
                uint32_t a = smemu32(&Vt[(t0 + (lane & 15)) * ALD + ni * 16 + 8 * (lane >> 4)]);
                ldsm4t(vb[ni], a);
            }
#pragma unroll
            for (int ni = 0; ni < 4; ni++) {
                const int jo = 2 * ni;
                mma16816(o[jo][0], o[jo][1], o[jo][2], o[jo][3],
                         ph[j][0], ph[j][1], ph[j + 1][0], ph[j + 1][1], vb[ni][0], vb[ni][1]);
                mma16816(o[jo + 1][0], o[jo + 1][1], o[jo + 1][2], o[jo + 1][3],
                         ph[j][0], ph[j][1], ph[j + 1][0], ph[j + 1][1], vb[ni][2], vb[ni][3]);
            }
        }
    }

    // ---- final row-sum reduction (once, not per tile) ----
    lsum0 += __shfl_xor_sync(0xffffffffu, lsum0, 1);
    lsum0 += __shfl_xor_sync(0xffffffffu, lsum0, 2);
    lsum8 += __shfl_xor_sync(0xffffffffu, lsum8, 1);
    lsum8 += __shfl_xor_sync(0xffffffffu, lsum8, 2);

    // ---- normalize + write half ctx ----
    const float inv0 = 1.f / lsum0;
    const float inv8 = 1.f / lsum8;
    __half* O0 = Og + ((size_t)b * SEQ + s0 + q0 + grp) * DIM + h * HD;
    __half* O8 = O0 + 8 * (size_t)DIM;
#pragma unroll
    for (int j = 0; j < 8; j++) {
        const int col = 8 * j + 2 * tig;
        *reinterpret_cast<__half2*>(&O0[col]) = __floats2half2_rn(o[j][0] * inv0, o[j][1] * inv0);
        *reinterpret_cast<__half2*>(&O8[col]) = __floats2half2_rn(o[j][2] * inv8, o[j][3] * inv8);
    }
}

// ---------------------------------------------------------------------------
// Launch
// ---------------------------------------------------------------------------
extern "C" void kernel_launch(void* const* d_in, const int* in_sizes, int n_in,
                              void* d_out, int out_size)
{
    const float* query = (const float*)d_in[0];
    const float* key   = (const float*)d_in[1];
    const float* value = (const float*)d_in[2];
    const int*   mask  = (const int*)  d_in[3];
    const float* Wq = (const float*)d_in[4];
    const float* bq = (const float*)d_in[5];
    const float* Wk = (const float*)d_in[6];
    const float* bk = (const float*)d_in[7];
    const float* Wv = (const float*)d_in[8];
    const float* bv = (const float*)d_in[9];
    const float* Wo = (const float*)d_in[10];
    const float* bo = (const float*)d_in[11];
    float* out = (float*)d_out;

    __half *pXh, *pWh, *pQKV, *pC;
    cudaGetSymbolAddress((void**)&pXh,  g_Xh);
    cudaGetSymbolAddress((void**)&pWh,  g_Wh);
    cudaGetSymbolAddress((void**)&pQKV, g_QKVh);
    cudaGetSymbolAddress((void**)&pC,   g_Ch);

    // pre-passes
    mask_bits_kernel<<<SEQ * SEQ / 256, 256>>>(mask);
    cvt_inputs<<<dim3(MTOT * DIM / 4 / 256, 3), 256>>>(query, key, value);
    cvt_weights<<<dim3(DIM * DIM / 4 / 256, 4), 256>>>(Wq, Wk, Wv, Wo);

    // fused QKV projections (all-half), log2-domain scale folded into Q
    cudaFuncSetAttribute(gemm_h<__half>, cudaFuncAttributeMaxDynamicSharedMemorySize, GEMM_SMEM);
    cudaFuncSetAttribute(gemm_h<float>,  cudaFuncAttributeMaxDynamicSharedMemorySize, GEMM_SMEM);
    dim3 qkv_grid(DIM / GBN, MTOT / GBM, 3);   // (8, 32, 3)
    gemm_h<__half><<<qkv_grid, 256, GEMM_SMEM>>>(
        pXh, (size_t)MTOT * DIM, pWh, (size_t)DIM * DIM,
        bq, bk, bv, pQKV, (size_t)MTOT * DIM,
        ATT_SCALE_LOG2E, 1.0f, 1.0f);

    // attention (3-stage KV pipeline, ex2-domain softmax)
    const int attn_smem = (128 + 2 * ASTG * 64) * ALD * (int)sizeof(__half);  // 73728 B
    cudaFuncSetAttribute(attn_mma, cudaFuncAttributeMaxDynamicSharedMemorySize, attn_smem);
    attn_mma<<<dim3(SEQ / 128, NH, BATCH), 256, attn_smem>>>(pC);

    // output projection (half A -> fp32 out)
    dim3 ogrid(DIM / GBN, MTOT / GBM, 1);
    gemm_h<float><<<ogrid, 256, GEMM_SMEM>>>(
        pC, 0, pWh + 3 * (size_t)DIM * DIM, 0,
        bo, bo, bo, out, 0,
        1.0f, 1.0f, 1.0f);
}